// round 11
// baseline (speedup 1.0000x reference)
#include <cuda_runtime.h>
#include <cuda_fp16.h>
#include <math.h>
#include <stdint.h>

#define NN    16384
#define EE    524288
#define BB    8
#define FIN   26
#define DD    128
#define HH    256
#define OUTD  64
#define NL    4
#define NRBF  16
#define KIN   272          // 2*DD + NRBF
#define KC1H  18           // msg W1 k-chunks of 16 (K padded to 288); kc16 = ef rows
#define KC2H  16           // msg GEMM2 / upd k-chunks of 16 (K = 256)

// ---------------- scratch (device globals; no allocation allowed) ----------
__device__ float g_h[NN * DD];
__device__ float g_agg[NN * DD];
__device__ float g_gsum[BB * DD];
__device__ float g_gcnt[BB];
// weights in fp16 B-fragment layout (packed half2 per uint)
__device__ unsigned int g_W1f[NL * KC1H * 16 * 32 * 4];   // msg W1 [l][kc][np16][t32][i4]
__device__ unsigned int g_W2f[NL * KC2H * 8 * 32 * 4];    // msg W2
__device__ unsigned int g_WU1f[NL * 16 * 16 * 32 * 4];    // upd W1
__device__ unsigned int g_WU2f[NL * 16 * 8 * 32 * 4];     // upd W2
// per-layer node-level partial activations (fp16, half2-packed: 128 uints/row)
__device__ unsigned int g_Xa[NN * 128];   // h@W1a + b1
__device__ unsigned int g_Xb[NN * 128];   // h@W1b

__device__ __forceinline__ float silu_f(float x) {
    return x * (1.0f / (1.0f + __expf(-x)));
}
__device__ __forceinline__ unsigned int packh2(float a, float b) {
    __half2 h = __floats2half2_rn(a, b);
    return *reinterpret_cast<unsigned int*>(&h);
}
__device__ __forceinline__ float2 uph2(unsigned int u) {
    return __half22float2(*reinterpret_cast<__half2*>(&u));
}
__device__ __forceinline__ unsigned int addh2_f32(unsigned int a, unsigned int b) {
    float2 fa = uph2(a), fb = uph2(b);
    return packh2(fa.x + fb.x, fa.y + fb.y);
}

// fp16 m16n8k16 MMA (baseline PTX, valid on compute_103)
__device__ __forceinline__ void mma16(float* c, uint4 a, uint32_t b0, uint32_t b1) {
    asm volatile(
        "mma.sync.aligned.m16n8k16.row.col.f32.f16.f16.f32 "
        "{%0,%1,%2,%3}, {%4,%5,%6,%7}, {%8,%9}, {%0,%1,%2,%3};"
        : "+f"(c[0]), "+f"(c[1]), "+f"(c[2]), "+f"(c[3])
        : "r"(a.x), "r"(a.y), "r"(a.z), "r"(a.w), "r"(b0), "r"(b1));
}

__device__ __forceinline__ void red4(float* p, float4 v) {
    asm volatile("red.global.add.v4.f32 [%0], {%1,%2,%3,%4};"
                 :: "l"(p), "f"(v.x), "f"(v.y), "f"(v.z), "f"(v.w) : "memory");
}

// ---------------- weight prep: fp16 fragment layout --------------------------
__global__ void prep1_k(const float* __restrict__ W1, unsigned int* __restrict__ Wf) {
    int idx = blockIdx.x * 256 + threadIdx.x;
    const int PER = KC1H * 16 * 32 * 4;
    if (idx >= NL * PER) return;
    int l = idx / PER, r = idx - l * PER;
    int kc = r / 2048;  r -= kc * 2048;
    int np = r / 128;   r -= np * 128;
    int t = r / 4, i = r & 3;
    int k0 = kc * 16 + (t & 3) * 2 + 8 * (i & 1);
    int n = np * 16 + ((i >> 1) << 3) + (t >> 2);
    float v0 = (k0 < KIN)     ? W1[((size_t)l * KIN + k0) * HH + n]     : 0.0f;
    float v1 = (k0 + 1 < KIN) ? W1[((size_t)l * KIN + k0 + 1) * HH + n] : 0.0f;
    Wf[idx] = packh2(v0, v1);
}
__global__ void prep2_k(const float* __restrict__ W2, unsigned int* __restrict__ Wf) {
    int idx = blockIdx.x * 256 + threadIdx.x;
    const int PER = KC2H * 8 * 32 * 4;
    if (idx >= NL * PER) return;
    int l = idx / PER, r = idx - l * PER;
    int kc = r / 1024;  r -= kc * 1024;
    int np = r / 128;   r -= np * 128;
    int t = r / 4, i = r & 3;
    int k0 = kc * 16 + (t & 3) * 2 + 8 * (i & 1);
    int n = np * 16 + ((i >> 1) << 3) + (t >> 2);
    Wf[idx] = packh2(W2[((size_t)l * HH + k0) * DD + n],
                     W2[((size_t)l * HH + k0 + 1) * DD + n]);
}
__global__ void prepU1_k(const float* __restrict__ W1, unsigned int* __restrict__ Wf) {
    int idx = blockIdx.x * 256 + threadIdx.x;
    const int PER = 16 * 16 * 32 * 4;
    if (idx >= NL * PER) return;
    int l = idx / PER, r = idx - l * PER;
    int kc = r / 2048;  r -= kc * 2048;
    int np = r / 128;   r -= np * 128;
    int t = r / 4, i = r & 3;
    int k0 = kc * 16 + (t & 3) * 2 + 8 * (i & 1);
    int n = np * 16 + ((i >> 1) << 3) + (t >> 2);
    Wf[idx] = packh2(W1[((size_t)l * 256 + k0) * HH + n],
                     W1[((size_t)l * 256 + k0 + 1) * HH + n]);
}
__global__ void prepU2_k(const float* __restrict__ W2, unsigned int* __restrict__ Wf) {
    int idx = blockIdx.x * 256 + threadIdx.x;
    const int PER = 16 * 8 * 32 * 4;
    if (idx >= NL * PER) return;
    int l = idx / PER, r = idx - l * PER;
    int kc = r / 1024;  r -= kc * 1024;
    int np = r / 128;   r -= np * 128;
    int t = r / 4, i = r & 3;
    int k0 = kc * 16 + (t & 3) * 2 + 8 * (i & 1);
    int n = np * 16 + ((i >> 1) << 3) + (t >> 2);
    Wf[idx] = packh2(W2[((size_t)l * HH + k0) * DD + n],
                     W2[((size_t)l * HH + k0 + 1) * DD + n]);
}

// ---------------- node embedding: (N,26) -> silu -> (N,128), fp32 ------------
__global__ void __launch_bounds__(128) embed_k(
    const float* __restrict__ nf,
    const float* __restrict__ W1, const float* __restrict__ b1,
    const float* __restrict__ W2, const float* __restrict__ b2,
    float* __restrict__ h)
{
    __shared__ __align__(16) float s_in[16 * FIN];
    __shared__ __align__(16) float s_hid[16 * DD];
    const int tid = threadIdx.x;
    const int n0 = blockIdx.x * 16;

    for (int idx = tid; idx < 16 * FIN; idx += 128) {
        int e = idx / FIN, k = idx - e * FIN;
        s_in[idx] = nf[(n0 + e) * FIN + k];
    }
    __syncthreads();

    const int j = tid;
    float acc[16];
#pragma unroll
    for (int e = 0; e < 16; e++) acc[e] = 0.0f;
    for (int k = 0; k < FIN; k++) {
        float w = W1[k * DD + j];
#pragma unroll
        for (int e = 0; e < 16; e++) acc[e] = fmaf(s_in[e * FIN + k], w, acc[e]);
    }
    float bb1 = b1[j];
#pragma unroll
    for (int e = 0; e < 16; e++) s_hid[e * DD + j] = silu_f(acc[e] + bb1);
    __syncthreads();

    float acc2[16];
#pragma unroll
    for (int e = 0; e < 16; e++) acc2[e] = 0.0f;
    const float4* sh4 = (const float4*)s_hid;
    for (int k4 = 0; k4 < DD / 4; k4++) {
        const float* wp = &W2[(k4 * 4) * DD + j];
        float w0 = wp[0], w1 = wp[DD], w2 = wp[2 * DD], w3 = wp[3 * DD];
#pragma unroll
        for (int e = 0; e < 16; e++) {
            float4 a = sh4[e * (DD / 4) + k4];
            acc2[e] = fmaf(a.x, w0, acc2[e]);
            acc2[e] = fmaf(a.y, w1, acc2[e]);
            acc2[e] = fmaf(a.z, w2, acc2[e]);
            acc2[e] = fmaf(a.w, w3, acc2[e]);
        }
    }
    float bb2 = b2[j];
#pragma unroll
    for (int e = 0; e < 16; e++) h[(n0 + e) * DD + j] = acc2[e] + bb2;
}

// ---------------- fp16 A-fragment staging helpers ----------------------------
__device__ __forceinline__ void stage_f4(unsigned int* sAu, int KC, int mt, int r,
                                         int k0, float4 v) {
    int kc = k0 >> 4;
    int c0 = k0 & 15;
    int t0 = ((r & 7) << 2) + ((c0 & 7) >> 1);
    int ii = (r >> 3) + ((c0 & 8) ? 2 : 0);
    unsigned int* base = sAu + ((mt * KC + kc) * 32) * 4 + ii;
    base[t0 * 4]       = packh2(v.x, v.y);
    base[(t0 + 1) * 4] = packh2(v.z, v.w);
}
// store two pre-packed half2 uints covering cols k0..k0+3 of row r
__device__ __forceinline__ void stage_u2(unsigned int* sAu, int KC, int mt, int r,
                                         int k0, unsigned int u01, unsigned int u23) {
    int kc = k0 >> 4;
    int c0 = k0 & 15;
    int t0 = ((r & 7) << 2) + ((c0 & 7) >> 1);
    int ii = (r >> 3) + ((c0 & 8) ? 2 : 0);
    unsigned int* base = sAu + ((mt * KC + kc) * 32) * 4 + ii;
    base[t0 * 4]       = u01;
    base[(t0 + 1) * 4] = u23;
}

// ---------------- per-layer node partials: Xa = h@W1a + b1, Xb = h@W1b -------
__global__ void __launch_bounds__(512, 1) xab_k(
    const float* __restrict__ h,
    const unsigned int* __restrict__ W1f, const float* __restrict__ b1,
    unsigned int* __restrict__ Xa, unsigned int* __restrict__ Xb)
{
    extern __shared__ __align__(16) unsigned int sAu[];   // 32768 B
    __shared__ float s_b1[HH];
    const int tid = threadIdx.x;
    const int n0 = blockIdx.x * 128;
    if (tid < HH) s_b1[tid] = b1[tid];

    {
        const int e = tid >> 2, q = tid & 3;
        const float* hs = h + (size_t)(n0 + e) * DD;
        const int r = e & 15, mt = e >> 4;
#pragma unroll
        for (int j = 0; j < 8; j++) {
            int k0 = j * 16 + q * 4;
            stage_f4(sAu, 8, mt, r, k0, *(const float4*)(hs + k0));
        }
    }
    __syncthreads();

    const int wid = tid >> 5, lane = tid & 31;
    const int wm = wid >> 3, wn = wid & 7;

#pragma unroll
    for (int p = 0; p < 2; p++) {
        float acc[4][4][4];
#pragma unroll
        for (int a = 0; a < 4; a++)
#pragma unroll
            for (int b = 0; b < 4; b++)
#pragma unroll
                for (int c = 0; c < 4; c++) acc[a][b][c] = 0.0f;
        const uint4* ap0 = (const uint4*)sAu + (wm * 4 + 0) * 8 * 32 + lane;
        const uint4* ap1 = (const uint4*)sAu + (wm * 4 + 1) * 8 * 32 + lane;
        const uint4* ap2 = (const uint4*)sAu + (wm * 4 + 2) * 8 * 32 + lane;
        const uint4* ap3 = (const uint4*)sAu + (wm * 4 + 3) * 8 * 32 + lane;
        const uint4* bp = (const uint4*)W1f + (p * 8) * 512 + (wn * 2) * 32 + lane;
#pragma unroll
        for (int kc = 0; kc < 8; kc++) {
            uint4 b0 = bp[kc * 512];
            uint4 b1v = bp[kc * 512 + 32];
            uint4 a0 = ap0[kc * 32], a1 = ap1[kc * 32];
            uint4 a2 = ap2[kc * 32], a3 = ap3[kc * 32];
            mma16(acc[0][0], a0, b0.x, b0.y);  mma16(acc[0][1], a0, b0.z, b0.w);
            mma16(acc[0][2], a0, b1v.x, b1v.y); mma16(acc[0][3], a0, b1v.z, b1v.w);
            mma16(acc[1][0], a1, b0.x, b0.y);  mma16(acc[1][1], a1, b0.z, b0.w);
            mma16(acc[1][2], a1, b1v.x, b1v.y); mma16(acc[1][3], a1, b1v.z, b1v.w);
            mma16(acc[2][0], a2, b0.x, b0.y);  mma16(acc[2][1], a2, b0.z, b0.w);
            mma16(acc[2][2], a2, b1v.x, b1v.y); mma16(acc[2][3], a2, b1v.z, b1v.w);
            mma16(acc[3][0], a3, b0.x, b0.y);  mma16(acc[3][1], a3, b0.z, b0.w);
            mma16(acc[3][2], a3, b1v.x, b1v.y); mma16(acc[3][3], a3, b1v.z, b1v.w);
        }
        unsigned int* out = p ? Xb : Xa;
#pragma unroll
        for (int mi = 0; mi < 4; mi++)
#pragma unroll
            for (int nf = 0; nf < 4; nf++) {
                int m_lo = wm * 64 + mi * 16 + (lane >> 2);
                int n = wn * 32 + nf * 8 + ((lane & 3) << 1);
                float a0 = (p == 0) ? s_b1[n] : 0.0f;
                float a1 = (p == 0) ? s_b1[n + 1] : 0.0f;
                out[(size_t)(n0 + m_lo) * 128 + (n >> 1)] =
                    packh2(acc[mi][nf][0] + a0, acc[mi][nf][1] + a1);
                out[(size_t)(n0 + m_lo + 8) * 128 + (n >> 1)] =
                    packh2(acc[mi][nf][2] + a0, acc[mi][nf][3] + a1);
            }
    }
}

// ---------------- message kernel: gather-add -> frags (in place) -------------
// 128 edges/CTA, 512 threads. Dynamic SMEM (uints):
//   [0, 16384)      sA2 : fp16 S/A2 frags [8mt][16kc][32][4]
//   [16384, 17408)  sEF : fp16 ef frags [8mt][1kc][32][4]
// After GEMM2, whole region reused as fp32 D2[128][132].
__global__ void __launch_bounds__(512, 1) msg_mma_k(
    const int* __restrict__ EI, const float* __restrict__ pos,
    const unsigned int* __restrict__ Xa, const unsigned int* __restrict__ Xb,
    const unsigned int* __restrict__ W1f,
    const unsigned int* __restrict__ W2f, const float* __restrict__ b2,
    float* __restrict__ agg)
{
    extern __shared__ __align__(16) unsigned int sMem[];
    unsigned int* sA2u = sMem;
    unsigned int* sEFu = sMem + 16384;
    float* sD2 = (float*)sMem;
    __shared__ float s_b2[DD];
    __shared__ int   s_dst[128];

    const int tid = threadIdx.x;
    const int e0 = blockIdx.x * 128;

    if (tid < DD) s_b2[tid] = b2[tid];
    if (tid < 128) s_dst[tid] = EI[EE + e0 + tid];

    // ---- gather: fp16(Xa[src]+Xb[dst]) straight into A2 fragment layout ----
    {
        const int e = tid >> 2, q = tid & 3;
        const int src = EI[e0 + e];
        const int dst = EI[EE + e0 + e];
        const uint4* pa = (const uint4*)(Xa + (size_t)src * 128) + q * 8;
        const uint4* pb = (const uint4*)(Xb + (size_t)dst * 128) + q * 8;
        const int r = e & 15, mt = e >> 4;
#pragma unroll
        for (int i = 0; i < 8; i++) {
            uint4 ua = pa[i], ub = pb[i];
            int c = q * 64 + i * 8;
            stage_u2(sA2u, KC2H, mt, r, c,
                     addh2_f32(ua.x, ub.x), addh2_f32(ua.y, ub.y));
            stage_u2(sA2u, KC2H, mt, r, c + 4,
                     addh2_f32(ua.z, ub.z), addh2_f32(ua.w, ub.w));
        }
        // RBF inline (each of the 4 threads/edge computes 4 of 16 values)
        float dx = pos[dst * 3 + 0] - pos[src * 3 + 0];
        float dy = pos[dst * 3 + 1] - pos[src * 3 + 1];
        float dz = pos[dst * 3 + 2] - pos[src * 3 + 2];
        float dist = sqrtf(dx * dx + dy * dy + dz * dz + 1e-12f);
        float env = (dist < 10.0f)
                        ? 0.5f * (cosf(3.14159265358979323846f * dist * 0.1f) + 1.0f)
                        : 0.0f;
        const float inv2w2 = 1.0f / (2.0f * 0.625f * 0.625f);
        float rv[4];
#pragma unroll
        for (int kk = 0; kk < 4; kk++) {
            float c2 = (10.0f / 15.0f) * (float)(q * 4 + kk);
            float t = dist - c2;
            rv[kk] = __expf(-t * t * inv2w2) * env;
        }
        stage_f4(sEFu, 1, e >> 4, e & 15, q * 4,
                 make_float4(rv[0], rv[1], rv[2], rv[3]));
    }
    __syncthreads();

    const int wid = tid >> 5, lane = tid & 31;
    const int wm = wid >> 3, wn = wid & 7;

    // ---- GEMM1c: ef @ W1c (single k-chunk, kc16 of W1f) ----
    float acc[4][4][4];
#pragma unroll
    for (int a = 0; a < 4; a++)
#pragma unroll
        for (int b = 0; b < 4; b++)
#pragma unroll
            for (int c = 0; c < 4; c++) acc[a][b][c] = 0.0f;
    {
        const uint4* bp = (const uint4*)W1f + 16 * 512 + (wn * 2) * 32 + lane;
        uint4 b0 = bp[0], b1v = bp[32];
        uint4 a0 = ((const uint4*)sEFu)[(wm * 4 + 0) * 32 + lane];
        uint4 a1 = ((const uint4*)sEFu)[(wm * 4 + 1) * 32 + lane];
        uint4 a2 = ((const uint4*)sEFu)[(wm * 4 + 2) * 32 + lane];
        uint4 a3 = ((const uint4*)sEFu)[(wm * 4 + 3) * 32 + lane];
        mma16(acc[0][0], a0, b0.x, b0.y);  mma16(acc[0][1], a0, b0.z, b0.w);
        mma16(acc[0][2], a0, b1v.x, b1v.y); mma16(acc[0][3], a0, b1v.z, b1v.w);
        mma16(acc[1][0], a1, b0.x, b0.y);  mma16(acc[1][1], a1, b0.z, b0.w);
        mma16(acc[1][2], a1, b1v.x, b1v.y); mma16(acc[1][3], a1, b1v.z, b1v.w);
        mma16(acc[2][0], a2, b0.x, b0.y);  mma16(acc[2][1], a2, b0.z, b0.w);
        mma16(acc[2][2], a2, b1v.x, b1v.y); mma16(acc[2][3], a2, b1v.z, b1v.w);
        mma16(acc[3][0], a3, b0.x, b0.y);  mma16(acc[3][1], a3, b0.z, b0.w);
        mma16(acc[3][2], a3, b1v.x, b1v.y); mma16(acc[3][3], a3, b1v.z, b1v.w);
    }

    // ---- epilogue1: in-place RMW: A2 = silu(acc + staged_sum) ----
#pragma unroll
    for (int mi = 0; mi < 4; mi++)
#pragma unroll
        for (int nf = 0; nf < 4; nf++) {
            int m_lo = wm * 64 + mi * 16 + (lane >> 2);
            int n = wn * 32 + nf * 8 + ((lane & 3) << 1);
            int mt2 = m_lo >> 4;
            int kc2 = n >> 4, c2 = n & 15;
            int t2 = ((m_lo & 7) << 2) + ((c2 & 7) >> 1);
            int ib = (c2 & 8) ? 2 : 0;
            unsigned int* base = sA2u + ((mt2 * KC2H + kc2) * 32 + t2) * 4 + ib;
            float2 f0 = uph2(base[0]);
            float2 f1 = uph2(base[1]);
            base[0] = packh2(silu_f(acc[mi][nf][0] + f0.x),
                             silu_f(acc[mi][nf][1] + f0.y));
            base[1] = packh2(silu_f(acc[mi][nf][2] + f1.x),
                             silu_f(acc[mi][nf][3] + f1.y));
        }
    __syncthreads();

    // ---- GEMM2: [128x256] @ [256x128] ----
    float acc2[4][2][4];
#pragma unroll
    for (int a = 0; a < 4; a++)
#pragma unroll
        for (int b = 0; b < 2; b++)
#pragma unroll
            for (int c = 0; c < 4; c++) acc2[a][b][c] = 0.0f;
    {
        const uint4* ap0 = (const uint4*)sA2u + (wm * 4 + 0) * KC2H * 32 + lane;
        const uint4* ap1 = (const uint4*)sA2u + (wm * 4 + 1) * KC2H * 32 + lane;
        const uint4* ap2 = (const uint4*)sA2u + (wm * 4 + 2) * KC2H * 32 + lane;
        const uint4* ap3 = (const uint4*)sA2u + (wm * 4 + 3) * KC2H * 32 + lane;
        const uint4* bp = (const uint4*)W2f + wn * 32 + lane;
#pragma unroll 2
        for (int kc = 0; kc < KC2H; kc++) {
            uint4 b = bp[kc * 256];
            uint4 a0 = ap0[kc * 32], a1 = ap1[kc * 32];
            uint4 a2 = ap2[kc * 32], a3 = ap3[kc * 32];
            mma16(acc2[0][0], a0, b.x, b.y);  mma16(acc2[0][1], a0, b.z, b.w);
            mma16(acc2[1][0], a1, b.x, b.y);  mma16(acc2[1][1], a1, b.z, b.w);
            mma16(acc2[2][0], a2, b.x, b.y);  mma16(acc2[2][1], a2, b.z, b.w);
            mma16(acc2[3][0], a3, b.x, b.y);  mma16(acc2[3][1], a3, b.z, b.w);
        }
    }
    __syncthreads();   // region reused as fp32 D2 staging

    // ---- epilogue2: stage D2+bias (padded stride 132), then red.v4 scatter --
#pragma unroll
    for (int mi = 0; mi < 4; mi++)
#pragma unroll
        for (int nf = 0; nf < 2; nf++)
#pragma unroll
            for (int j = 0; j < 4; j++) {
                int m = wm * 64 + mi * 16 + (lane >> 2) + ((j >> 1) << 3);
                int n = wn * 16 + nf * 8 + ((lane & 3) << 1) + (j & 1);
                sD2[m * 132 + n] = acc2[mi][nf][j] + s_b2[n];
            }
    __syncthreads();
    {
        const int cc = tid & 31;
        const int r0 = tid >> 5;
#pragma unroll
        for (int it = 0; it < 8; it++) {
            int r = r0 + it * 16;
            float4 v = *(const float4*)(sD2 + r * 132 + cc * 4);
            red4(agg + (size_t)s_dst[r] * DD + cc * 4, v);
        }
    }
}

// ---------------- fp16 tensor-core update MLP (residual) ---------------------
__global__ void __launch_bounds__(512, 1) upd_mma_k(
    float* __restrict__ h, const float* __restrict__ agg,
    const unsigned int* __restrict__ W1f, const float* __restrict__ b1,
    const unsigned int* __restrict__ W2f, const float* __restrict__ b2)
{
    extern __shared__ __align__(16) unsigned int sAu[];   // 69632 B
    float* sAf = (float*)sAu;
    __shared__ float s_b1[HH];
    __shared__ float s_b2[DD];

    const int tid = threadIdx.x;
    const int n0 = blockIdx.x * 128;

    if (tid < HH) s_b1[tid] = b1[tid];
    if (tid < DD) s_b2[tid] = b2[tid];

    {
        const int e = tid >> 2, q = tid & 3;
        const float* hs = h + (size_t)(n0 + e) * DD;
        const float* ag = agg + (size_t)(n0 + e) * DD;
        const int r = e & 15, mt = e >> 4;
#pragma unroll
        for (int j = 0; j < 16; j++) {
            int k0 = j * 16 + q * 4;
            float4 v = (k0 < 128) ? *(const float4*)(hs + k0)
                                  : *(const float4*)(ag + (k0 - 128));
            stage_f4(sAu, 16, mt, r, k0, v);
        }
    }
    __syncthreads();

    const int wid = tid >> 5, lane = tid & 31;
    const int wm = wid >> 3, wn = wid & 7;

    float acc[4][4][4];
#pragma unroll
    for (int a = 0; a < 4; a++)
#pragma unroll
        for (int b = 0; b < 4; b++)
#pragma unroll
            for (int c = 0; c < 4; c++) acc[a][b][c] = 0.0f;
    {
        const uint4* ap0 = (const uint4*)sAu + (wm * 4 + 0) * 16 * 32 + lane;
        const uint4* ap1 = (const uint4*)sAu + (wm * 4 + 1) * 16 * 32 + lane;
        const uint4* ap2 = (const uint4*)sAu + (wm * 4 + 2) * 16 * 32 + lane;
        const uint4* ap3 = (const uint4*)sAu + (wm * 4 + 3) * 16 * 32 + lane;
        const uint4* bp = (const uint4*)W1f + (wn * 2) * 32 + lane;
#pragma unroll 2
        for (int kc = 0; kc < 16; kc++) {
            uint4 b0 = bp[kc * 512];
            uint4 b1v = bp[kc * 512 + 32];
            uint4 a0 = ap0[kc * 32], a1 = ap1[kc * 32];
            uint4 a2 = ap2[kc * 32], a3 = ap3[kc * 32];
            mma16(acc[0][0], a0, b0.x, b0.y);  mma16(acc[0][1], a0, b0.z, b0.w);
            mma16(acc[0][2], a0, b1v.x, b1v.y); mma16(acc[0][3], a0, b1v.z, b1v.w);
            mma16(acc[1][0], a1, b0.x, b0.y);  mma16(acc[1][1], a1, b0.z, b0.w);
            mma16(acc[1][2], a1, b1v.x, b1v.y); mma16(acc[1][3], a1, b1v.z, b1v.w);
            mma16(acc[2][0], a2, b0.x, b0.y);  mma16(acc[2][1], a2, b0.z, b0.w);
            mma16(acc[2][2], a2, b1v.x, b1v.y); mma16(acc[2][3], a2, b1v.z, b1v.w);
            mma16(acc[3][0], a3, b0.x, b0.y);  mma16(acc[3][1], a3, b0.z, b0.w);
            mma16(acc[3][2], a3, b1v.x, b1v.y); mma16(acc[3][3], a3, b1v.z, b1v.w);
        }
    }
    __syncthreads();

#pragma unroll
    for (int mi = 0; mi < 4; mi++)
#pragma unroll
        for (int nf = 0; nf < 4; nf++) {
            int m_lo = wm * 64 + mi * 16 + (lane >> 2);
            int n = wn * 32 + nf * 8 + ((lane & 3) << 1);
            float y00 = silu_f(acc[mi][nf][0] + s_b1[n]);
            float y01 = silu_f(acc[mi][nf][1] + s_b1[n + 1]);
            float y10 = silu_f(acc[mi][nf][2] + s_b1[n]);
            float y11 = silu_f(acc[mi][nf][3] + s_b1[n + 1]);
            int mt2 = m_lo >> 4;
            int kc2 = n >> 4, c2 = n & 15;
            int t2 = ((m_lo & 7) << 2) + ((c2 & 7) >> 1);
            int ib = (c2 & 8) ? 2 : 0;
            unsigned int* base = sAu + ((mt2 * 16 + kc2) * 32 + t2) * 4 + ib;
            base[0] = packh2(y00, y01);
            base[1] = packh2(y10, y11);
        }
    __syncthreads();

    float acc2[4][2][4];
#pragma unroll
    for (int a = 0; a < 4; a++)
#pragma unroll
        for (int b = 0; b < 2; b++)
#pragma unroll
            for (int c = 0; c < 4; c++) acc2[a][b][c] = 0.0f;
    {
        const uint4* ap0 = (const uint4*)sAu + (wm * 4 + 0) * 16 * 32 + lane;
        const uint4* ap1 = (const uint4*)sAu + (wm * 4 + 1) * 16 * 32 + lane;
        const uint4* ap2 = (const uint4*)sAu + (wm * 4 + 2) * 16 * 32 + lane;
        const uint4* ap3 = (const uint4*)sAu + (wm * 4 + 3) * 16 * 32 + lane;
        const uint4* bp = (const uint4*)W2f + wn * 32 + lane;
#pragma unroll 2
        for (int kc = 0; kc < 16; kc++) {
            uint4 b = bp[kc * 256];
            uint4 a0 = ap0[kc * 32], a1 = ap1[kc * 32];
            uint4 a2 = ap2[kc * 32], a3 = ap3[kc * 32];
            mma16(acc2[0][0], a0, b.x, b.y);  mma16(acc2[0][1], a0, b.z, b.w);
            mma16(acc2[1][0], a1, b.x, b.y);  mma16(acc2[1][1], a1, b.z, b.w);
            mma16(acc2[2][0], a2, b.x, b.y);  mma16(acc2[2][1], a2, b.z, b.w);
            mma16(acc2[3][0], a3, b.x, b.y);  mma16(acc2[3][1], a3, b.z, b.w);
        }
    }
    __syncthreads();

#pragma unroll
    for (int mi = 0; mi < 4; mi++)
#pragma unroll
        for (int nf = 0; nf < 2; nf++)
#pragma unroll
            for (int j = 0; j < 4; j++) {
                int m = wm * 64 + mi * 16 + (lane >> 2) + ((j >> 1) << 3);
                int n = wn * 16 + nf * 8 + ((lane & 3) << 1) + (j & 1);
                sAf[m * 132 + n] = acc2[mi][nf][j] + s_b2[n];
            }
    __syncthreads();
    {
        const int cc = tid & 31;
        const int r0 = tid >> 5;
#pragma unroll
        for (int it = 0; it < 8; it++) {
            int r = r0 + it * 16;
            float4 v = *(const float4*)(sAf + r * 132 + cc * 4);
            float* hp = h + (size_t)(n0 + r) * DD + cc * 4;
            float4 o = *(float4*)hp;
            o.x += v.x; o.y += v.y; o.z += v.z; o.w += v.w;
            *(float4*)hp = o;
        }
    }
}

// ---------------- per-graph counts ------------------------------------------
__global__ void cnt_k(const int* __restrict__ batch, float* __restrict__ cnt)
{
    int n = blockIdx.x * blockDim.x + threadIdx.x;
    if (n < NN) atomicAdd(&cnt[batch[n]], 1.0f);
}

// ---------------- per-graph feature sums ------------------------------------
__global__ void __launch_bounds__(128) gsum_k(
    const float* __restrict__ h, const int* __restrict__ batch,
    float* __restrict__ gsum)
{
    const int j = threadIdx.x;
    const int n0 = blockIdx.x * 32;
    int curb = batch[n0];
    float acc = 0.0f;
    for (int i = 0; i < 32; i++) {
        int n = n0 + i;
        int b = batch[n];
        if (b != curb) {
            atomicAdd(&gsum[curb * DD + j], acc);
            acc = 0.0f;
            curb = b;
        }
        acc += h[n * DD + j];
    }
    atomicAdd(&gsum[curb * DD + j], acc);
}

// ---------------- readout MLP (single block) --------------------------------
__global__ void __launch_bounds__(256) final_k(
    const float* __restrict__ gsum, const float* __restrict__ cnt,
    const float* __restrict__ W1, const float* __restrict__ b1,
    const float* __restrict__ W2, const float* __restrict__ b2,
    float* __restrict__ out)
{
    __shared__ float sg[BB * DD];
    __shared__ float sh[BB * HH];
    const int tid = threadIdx.x;

    for (int idx = tid; idx < BB * DD; idx += 256) {
        int b = idx >> 7;
        sg[idx] = gsum[idx] / fmaxf(cnt[b], 1.0f);
    }
    __syncthreads();

    {
        const int j = tid;
        float acc[BB];
#pragma unroll
        for (int b = 0; b < BB; b++) acc[b] = 0.0f;
        for (int k = 0; k < DD; k++) {
            float w = W1[k * HH + j];
#pragma unroll
            for (int b = 0; b < BB; b++) acc[b] = fmaf(sg[b * DD + k], w, acc[b]);
        }
        float bb = b1[j];
#pragma unroll
        for (int b = 0; b < BB; b++) sh[b * HH + j] = silu_f(acc[b] + bb);
    }
    __syncthreads();

    if (tid < OUTD) {
        const int j = tid;
        float acc[BB];
#pragma unroll
        for (int b = 0; b < BB; b++) acc[b] = 0.0f;
        for (int k = 0; k < HH; k++) {
            float w = W2[k * OUTD + j];
#pragma unroll
            for (int b = 0; b < BB; b++) acc[b] = fmaf(sh[b * HH + k], w, acc[b]);
        }
        float bb = b2[j];
#pragma unroll
        for (int b = 0; b < BB; b++) out[b * OUTD + j] = acc[b] + bb;
    }
}

// ---------------- launch -----------------------------------------------------
#define SMEM_MSG 69632
#define SMEM_UPD 69632
#define SMEM_XAB 32768

extern "C" void kernel_launch(void* const* d_in, const int* in_sizes, int n_in,
                              void* d_out, int out_size)
{
    const float* pos    = (const float*)d_in[0];
    const float* nf     = (const float*)d_in[1];
    const int*   EI     = (const int*)d_in[2];
    const int*   batch  = (const int*)d_in[3];
    const float* emb_W1 = (const float*)d_in[4];
    const float* emb_b1 = (const float*)d_in[5];
    const float* emb_W2 = (const float*)d_in[6];
    const float* emb_b2 = (const float*)d_in[7];
    const float* msg_W1 = (const float*)d_in[8];
    const float* msg_b1 = (const float*)d_in[9];
    const float* msg_W2 = (const float*)d_in[10];
    const float* msg_b2 = (const float*)d_in[11];
    const float* upd_W1 = (const float*)d_in[12];
    const float* upd_b1 = (const float*)d_in[13];
    const float* upd_W2 = (const float*)d_in[14];
    const float* upd_b2 = (const float*)d_in[15];
    const float* r_W1   = (const float*)d_in[16];
    const float* r_b1   = (const float*)d_in[17];
    const float* r_W2   = (const float*)d_in[18];
    const float* r_b2   = (const float*)d_in[19];
    float* out = (float*)d_out;

    void *p_h, *p_agg, *p_gsum, *p_gcnt, *p_w1f, *p_w2f, *p_wu1f, *p_wu2f, *p_xa, *p_xb;
    cudaGetSymbolAddress(&p_h, g_h);
    cudaGetSymbolAddress(&p_agg, g_agg);
    cudaGetSymbolAddress(&p_gsum, g_gsum);
    cudaGetSymbolAddress(&p_gcnt, g_gcnt);
    cudaGetSymbolAddress(&p_w1f, g_W1f);
    cudaGetSymbolAddress(&p_w2f, g_W2f);
    cudaGetSymbolAddress(&p_wu1f, g_WU1f);
    cudaGetSymbolAddress(&p_wu2f, g_WU2f);
    cudaGetSymbolAddress(&p_xa, g_Xa);
    cudaGetSymbolAddress(&p_xb, g_Xb);
    float* h    = (float*)p_h;
    float* agg  = (float*)p_agg;
    float* gsum = (float*)p_gsum;
    float* gcnt = (float*)p_gcnt;
    unsigned int* W1f  = (unsigned int*)p_w1f;
    unsigned int* W2f  = (unsigned int*)p_w2f;
    unsigned int* WU1f = (unsigned int*)p_wu1f;
    unsigned int* WU2f = (unsigned int*)p_wu2f;
    unsigned int* Xa   = (unsigned int*)p_xa;
    unsigned int* Xb   = (unsigned int*)p_xb;

    cudaFuncSetAttribute(msg_mma_k, cudaFuncAttributeMaxDynamicSharedMemorySize, SMEM_MSG);
    cudaFuncSetAttribute(upd_mma_k, cudaFuncAttributeMaxDynamicSharedMemorySize, SMEM_UPD);

    prep1_k<<<(NL * KC1H * 16 * 32 * 4 + 255) / 256, 256>>>(msg_W1, W1f);
    prep2_k<<<(NL * KC2H * 8 * 32 * 4 + 255) / 256, 256>>>(msg_W2, W2f);
    prepU1_k<<<(NL * 16 * 16 * 32 * 4 + 255) / 256, 256>>>(upd_W1, WU1f);
    prepU2_k<<<(NL * 16 * 8 * 32 * 4 + 255) / 256, 256>>>(upd_W2, WU2f);
    embed_k<<<NN / 16, 128>>>(nf, emb_W1, emb_b1, emb_W2, emb_b2, h);

    for (int l = 0; l < NL; l++) {
        cudaMemsetAsync(agg, 0, (size_t)NN * DD * sizeof(float), 0);
        xab_k<<<NN / 128, 512, SMEM_XAB>>>(
            h,
            W1f + (size_t)l * KC1H * 16 * 32 * 4,
            msg_b1 + (size_t)l * HH,
            Xa, Xb);
        msg_mma_k<<<EE / 128, 512, SMEM_MSG>>>(
            EI, pos, Xa, Xb,
            W1f + (size_t)l * KC1H * 16 * 32 * 4,
            W2f + (size_t)l * KC2H * 8 * 32 * 4,
            msg_b2 + (size_t)l * DD,
            agg);
        upd_mma_k<<<NN / 128, 512, SMEM_UPD>>>(
            h, agg,
            WU1f + (size_t)l * 16 * 16 * 32 * 4,
            upd_b1 + (size_t)l * HH,
            WU2f + (size_t)l * 16 * 8 * 32 * 4,
            upd_b2 + (size_t)l * DD);
    }

    cudaMemsetAsync(gsum, 0, (size_t)BB * DD * sizeof(float), 0);
    cudaMemsetAsync(gcnt, 0, (size_t)BB * sizeof(float), 0);
    cnt_k<<<NN / 256, 256>>>(batch, gcnt);
    gsum_k<<<NN / 32, 128>>>(h, batch, gsum);
    final_k<<<1, 256>>>(gsum, gcnt, r_W1, r_b1, r_W2, r_b2, out);
}

// round 12
// speedup vs baseline: 1.7430x; 1.7430x over previous
#include <cuda_runtime.h>
#include <cuda_fp16.h>
#include <math.h>
#include <stdint.h>

#define NN    16384
#define EE    524288
#define BB    8
#define FIN   26
#define DD    128
#define HH    256
#define OUTD  64
#define NL    4
#define NRBF  16
#define KIN   272          // 2*DD + NRBF = exactly 17 chunks of 16
#define KC1H  17           // msg GEMM1 k-chunks of 16 (no padding; kc16 = ef)
#define KC2H  16           // msg GEMM2 / upd k-chunks of 16 (K = 256)

// ---------------- scratch (device globals; no allocation allowed) ----------
__device__ float g_h[NN * DD];
__device__ float g_agg[NN * DD];
__device__ float g_gsum[BB * DD];
__device__ float g_gcnt[BB];
// weights in fp16 B-fragment layout (packed half2 per uint)
__device__ unsigned int g_W1f[NL * KC1H * 16 * 32 * 4];   // msg GEMM1 [l][kc][np16][t32][i4]
__device__ unsigned int g_W2f[NL * KC2H * 8 * 32 * 4];    // msg GEMM2
__device__ unsigned int g_WU1f[NL * 16 * 16 * 32 * 4];    // upd GEMM1
__device__ unsigned int g_WU2f[NL * 16 * 8 * 32 * 4];     // upd GEMM2

__device__ __forceinline__ float silu_f(float x) {
    return x * (1.0f / (1.0f + __expf(-x)));
}
__device__ __forceinline__ unsigned int packh2(float a, float b) {
    __half2 h = __floats2half2_rn(a, b);
    return *reinterpret_cast<unsigned int*>(&h);
}

// fp16 m16n8k16 MMA (baseline PTX, valid on compute_103)
__device__ __forceinline__ void mma16(float* c, uint4 a, uint32_t b0, uint32_t b1) {
    asm volatile(
        "mma.sync.aligned.m16n8k16.row.col.f32.f16.f16.f32 "
        "{%0,%1,%2,%3}, {%4,%5,%6,%7}, {%8,%9}, {%0,%1,%2,%3};"
        : "+f"(c[0]), "+f"(c[1]), "+f"(c[2]), "+f"(c[3])
        : "r"(a.x), "r"(a.y), "r"(a.z), "r"(a.w), "r"(b0), "r"(b1));
}

__device__ __forceinline__ void red4(float* p, float4 v) {
    asm volatile("red.global.add.v4.f32 [%0], {%1,%2,%3,%4};"
                 :: "l"(p), "f"(v.x), "f"(v.y), "f"(v.z), "f"(v.w) : "memory");
}

// ---------------- weight prep: fp16 fragment layout --------------------------
// B-frag m16n8k16 (col-major B, shape k16 x n8):
//   b0: n = t/4, k = (t%4)*2 + {0,1};  b1: n = t/4, k = 8 + (t%4)*2 + {0,1}
// uint4 per (kc,np,t): i=0,1 -> n-frag np*2 (b0,b1); i=2,3 -> n-frag np*2+1
__global__ void prep1_k(const float* __restrict__ W1, unsigned int* __restrict__ Wf) {
    int idx = blockIdx.x * 256 + threadIdx.x;
    const int PER = KC1H * 16 * 32 * 4;
    if (idx >= NL * PER) return;
    int l = idx / PER, r = idx - l * PER;
    int kc = r / 2048;  r -= kc * 2048;
    int np = r / 128;   r -= np * 128;
    int t = r / 4, i = r & 3;
    int k0 = kc * 16 + (t & 3) * 2 + 8 * (i & 1);
    int n = np * 16 + ((i >> 1) << 3) + (t >> 2);
    float v0 = (k0 < KIN)     ? W1[((size_t)l * KIN + k0) * HH + n]     : 0.0f;
    float v1 = (k0 + 1 < KIN) ? W1[((size_t)l * KIN + k0 + 1) * HH + n] : 0.0f;
    Wf[idx] = packh2(v0, v1);
}
__global__ void prep2_k(const float* __restrict__ W2, unsigned int* __restrict__ Wf) {
    int idx = blockIdx.x * 256 + threadIdx.x;
    const int PER = KC2H * 8 * 32 * 4;
    if (idx >= NL * PER) return;
    int l = idx / PER, r = idx - l * PER;
    int kc = r / 1024;  r -= kc * 1024;
    int np = r / 128;   r -= np * 128;
    int t = r / 4, i = r & 3;
    int k0 = kc * 16 + (t & 3) * 2 + 8 * (i & 1);
    int n = np * 16 + ((i >> 1) << 3) + (t >> 2);
    Wf[idx] = packh2(W2[((size_t)l * HH + k0) * DD + n],
                     W2[((size_t)l * HH + k0 + 1) * DD + n]);
}
__global__ void prepU1_k(const float* __restrict__ W1, unsigned int* __restrict__ Wf) {
    int idx = blockIdx.x * 256 + threadIdx.x;
    const int PER = 16 * 16 * 32 * 4;
    if (idx >= NL * PER) return;
    int l = idx / PER, r = idx - l * PER;
    int kc = r / 2048;  r -= kc * 2048;
    int np = r / 128;   r -= np * 128;
    int t = r / 4, i = r & 3;
    int k0 = kc * 16 + (t & 3) * 2 + 8 * (i & 1);
    int n = np * 16 + ((i >> 1) << 3) + (t >> 2);
    Wf[idx] = packh2(W1[((size_t)l * 256 + k0) * HH + n],
                     W1[((size_t)l * 256 + k0 + 1) * HH + n]);
}
__global__ void prepU2_k(const float* __restrict__ W2, unsigned int* __restrict__ Wf) {
    int idx = blockIdx.x * 256 + threadIdx.x;
    const int PER = 16 * 8 * 32 * 4;
    if (idx >= NL * PER) return;
    int l = idx / PER, r = idx - l * PER;
    int kc = r / 1024;  r -= kc * 1024;
    int np = r / 128;   r -= np * 128;
    int t = r / 4, i = r & 3;
    int k0 = kc * 16 + (t & 3) * 2 + 8 * (i & 1);
    int n = np * 16 + ((i >> 1) << 3) + (t >> 2);
    Wf[idx] = packh2(W2[((size_t)l * HH + k0) * DD + n],
                     W2[((size_t)l * HH + k0 + 1) * DD + n]);
}

// ---------------- node embedding: (N,26) -> silu -> (N,128), fp32 ------------
__global__ void __launch_bounds__(128) embed_k(
    const float* __restrict__ nf,
    const float* __restrict__ W1, const float* __restrict__ b1,
    const float* __restrict__ W2, const float* __restrict__ b2,
    float* __restrict__ h)
{
    __shared__ __align__(16) float s_in[16 * FIN];
    __shared__ __align__(16) float s_hid[16 * DD];
    const int tid = threadIdx.x;
    const int n0 = blockIdx.x * 16;

    for (int idx = tid; idx < 16 * FIN; idx += 128) {
        int e = idx / FIN, k = idx - e * FIN;
        s_in[idx] = nf[(n0 + e) * FIN + k];
    }
    __syncthreads();

    const int j = tid;
    float acc[16];
#pragma unroll
    for (int e = 0; e < 16; e++) acc[e] = 0.0f;
    for (int k = 0; k < FIN; k++) {
        float w = W1[k * DD + j];
#pragma unroll
        for (int e = 0; e < 16; e++) acc[e] = fmaf(s_in[e * FIN + k], w, acc[e]);
    }
    float bb1 = b1[j];
#pragma unroll
    for (int e = 0; e < 16; e++) s_hid[e * DD + j] = silu_f(acc[e] + bb1);
    __syncthreads();

    float acc2[16];
#pragma unroll
    for (int e = 0; e < 16; e++) acc2[e] = 0.0f;
    const float4* sh4 = (const float4*)s_hid;
    for (int k4 = 0; k4 < DD / 4; k4++) {
        const float* wp = &W2[(k4 * 4) * DD + j];
        float w0 = wp[0], w1 = wp[DD], w2 = wp[2 * DD], w3 = wp[3 * DD];
#pragma unroll
        for (int e = 0; e < 16; e++) {
            float4 a = sh4[e * (DD / 4) + k4];
            acc2[e] = fmaf(a.x, w0, acc2[e]);
            acc2[e] = fmaf(a.y, w1, acc2[e]);
            acc2[e] = fmaf(a.z, w2, acc2[e]);
            acc2[e] = fmaf(a.w, w3, acc2[e]);
        }
    }
    float bb2 = b2[j];
#pragma unroll
    for (int e = 0; e < 16; e++) h[(n0 + e) * DD + j] = acc2[e] + bb2;
}

// ---------------- fp16 A-fragment staging helper -----------------------------
// A-frag m16n8k16 (row-major 16x16): element (r,c):
//   t = (r%8)*4 + ((c%8)>>1); i = (r>>3) + 2*(c>=8); half = c&1
__device__ __forceinline__ void stage_f4(unsigned int* sAu, int KC, int mt, int r,
                                         int k0, float4 v) {
    int kc = k0 >> 4;
    int c0 = k0 & 15;
    int t0 = ((r & 7) << 2) + ((c0 & 7) >> 1);
    int ii = (r >> 3) + ((c0 & 8) ? 2 : 0);
    unsigned int* base = sAu + ((mt * KC + kc) * 32) * 4 + ii;
    base[t0 * 4]       = packh2(v.x, v.y);
    base[(t0 + 1) * 4] = packh2(v.z, v.w);
}

// ---------------- fp16 tensor-core message MLP + v4-red scatter --------------
// CTA: 128 edges, 512 threads = 16 warps (2M x 8N). RBF computed inline.
__global__ void __launch_bounds__(512, 1) msg_mma_k(
    const int* __restrict__ EI, const float* __restrict__ pos,
    const float* __restrict__ h,
    const unsigned int* __restrict__ W1f, const float* __restrict__ b1,
    const unsigned int* __restrict__ W2f, const float* __restrict__ b2,
    float* __restrict__ agg)
{
    extern __shared__ __align__(16) unsigned int sAu[];   // 69632 B (KC1H layout)
    float* sAf = (float*)sAu;
    __shared__ float s_b1[HH];
    __shared__ float s_b2[DD];
    __shared__ int   s_dst[128];

    const int tid = threadIdx.x;
    const int e0 = blockIdx.x * 128;

    if (tid < HH) s_b1[tid] = b1[tid];
    if (tid < DD) s_b2[tid] = b2[tid];
    if (tid < 128) s_dst[tid] = EI[EE + e0 + tid];

    // ---- stage gathered edge features into fp16 A-fragment layout ----
    {
        const int e = tid >> 2;
        const int q = tid & 3;
        const int src = EI[e0 + e];
        const int dst = EI[EE + e0 + e];
        const float* hs = h + (size_t)src * DD;
        const float* hd = h + (size_t)dst * DD;
        const int r = e & 15, mt = e >> 4;
#pragma unroll
        for (int j = 0; j < 16; j++) {
            int k0 = j * 16 + q * 4;       // 0..252, covers cols 0..255
            float4 v = (k0 < 128) ? *(const float4*)(hs + k0)
                                  : *(const float4*)(hd + (k0 - 128));
            stage_f4(sAu, KC1H, mt, r, k0, v);
        }
        // chunk kc=16: RBF features (4 values per staging thread)
        float dx = pos[dst * 3 + 0] - pos[src * 3 + 0];
        float dy = pos[dst * 3 + 1] - pos[src * 3 + 1];
        float dz = pos[dst * 3 + 2] - pos[src * 3 + 2];
        float dist = sqrtf(dx * dx + dy * dy + dz * dz + 1e-12f);
        float env = (dist < 10.0f)
                        ? 0.5f * (cosf(3.14159265358979323846f * dist * 0.1f) + 1.0f)
                        : 0.0f;
        const float inv2w2 = 1.0f / (2.0f * 0.625f * 0.625f);
        float rv[4];
#pragma unroll
        for (int kk = 0; kk < 4; kk++) {
            float c = (10.0f / 15.0f) * (float)(q * 4 + kk);
            float t = dist - c;
            rv[kk] = __expf(-t * t * inv2w2) * env;
        }
        stage_f4(sAu, KC1H, mt, r, 256 + q * 4,
                 make_float4(rv[0], rv[1], rv[2], rv[3]));
    }
    __syncthreads();

    const int wid = tid >> 5, lane = tid & 31;
    const int wm = wid >> 3, wn = wid & 7;   // 2 M-tiles(64) x 8 N-tiles(32)

    // ================= GEMM1: M-tile 64 (4 mfrags), N-tile 32 (2 npairs) ====
    float acc[4][4][4];
#pragma unroll
    for (int a = 0; a < 4; a++)
#pragma unroll
        for (int b = 0; b < 4; b++)
#pragma unroll
            for (int c = 0; c < 4; c++) acc[a][b][c] = 0.0f;
    {
        const uint4* ap0 = (const uint4*)sAu + (wm * 4 + 0) * KC1H * 32 + lane;
        const uint4* ap1 = (const uint4*)sAu + (wm * 4 + 1) * KC1H * 32 + lane;
        const uint4* ap2 = (const uint4*)sAu + (wm * 4 + 2) * KC1H * 32 + lane;
        const uint4* ap3 = (const uint4*)sAu + (wm * 4 + 3) * KC1H * 32 + lane;
        const uint4* bp = (const uint4*)W1f + (wn * 2) * 32 + lane;
#pragma unroll 2
        for (int kc = 0; kc < KC1H; kc++) {
            uint4 b0 = bp[kc * 512];
            uint4 b1v = bp[kc * 512 + 32];
            uint4 a0 = ap0[kc * 32], a1 = ap1[kc * 32];
            uint4 a2 = ap2[kc * 32], a3 = ap3[kc * 32];
            mma16(acc[0][0], a0, b0.x, b0.y);  mma16(acc[0][1], a0, b0.z, b0.w);
            mma16(acc[0][2], a0, b1v.x, b1v.y); mma16(acc[0][3], a0, b1v.z, b1v.w);
            mma16(acc[1][0], a1, b0.x, b0.y);  mma16(acc[1][1], a1, b0.z, b0.w);
            mma16(acc[1][2], a1, b1v.x, b1v.y); mma16(acc[1][3], a1, b1v.z, b1v.w);
            mma16(acc[2][0], a2, b0.x, b0.y);  mma16(acc[2][1], a2, b0.z, b0.w);
            mma16(acc[2][2], a2, b1v.x, b1v.y); mma16(acc[2][3], a2, b1v.z, b1v.w);
            mma16(acc[3][0], a3, b0.x, b0.y);  mma16(acc[3][1], a3, b0.z, b0.w);
            mma16(acc[3][2], a3, b1v.x, b1v.y); mma16(acc[3][3], a3, b1v.z, b1v.w);
        }
    }
    __syncthreads();

    // ---- epilogue1: bias + silu -> A2 fp16 fragment layout (KC2H) ----
#pragma unroll
    for (int mi = 0; mi < 4; mi++)
#pragma unroll
        for (int nf = 0; nf < 4; nf++) {
            int m_lo = wm * 64 + mi * 16 + (lane >> 2);
            int n = wn * 32 + nf * 8 + ((lane & 3) << 1);
            float y00 = silu_f(acc[mi][nf][0] + s_b1[n]);
            float y01 = silu_f(acc[mi][nf][1] + s_b1[n + 1]);
            float y10 = silu_f(acc[mi][nf][2] + s_b1[n]);
            float y11 = silu_f(acc[mi][nf][3] + s_b1[n + 1]);
            int mt2 = m_lo >> 4;
            int kc2 = n >> 4, c2 = n & 15;
            int t2 = ((m_lo & 7) << 2) + ((c2 & 7) >> 1);
            int ib = (c2 & 8) ? 2 : 0;
            unsigned int* base = sAu + ((mt2 * KC2H + kc2) * 32 + t2) * 4 + ib;
            base[0] = packh2(y00, y01);
            base[1] = packh2(y10, y11);
        }
    __syncthreads();

    // ================= GEMM2: M-tile 64, N-tile 16 (1 npair) ================
    float acc2[4][2][4];
#pragma unroll
    for (int a = 0; a < 4; a++)
#pragma unroll
        for (int b = 0; b < 2; b++)
#pragma unroll
            for (int c = 0; c < 4; c++) acc2[a][b][c] = 0.0f;
    {
        const uint4* ap0 = (const uint4*)sAu + (wm * 4 + 0) * KC2H * 32 + lane;
        const uint4* ap1 = (const uint4*)sAu + (wm * 4 + 1) * KC2H * 32 + lane;
        const uint4* ap2 = (const uint4*)sAu + (wm * 4 + 2) * KC2H * 32 + lane;
        const uint4* ap3 = (const uint4*)sAu + (wm * 4 + 3) * KC2H * 32 + lane;
        const uint4* bp = (const uint4*)W2f + wn * 32 + lane;
#pragma unroll 2
        for (int kc = 0; kc < KC2H; kc++) {
            uint4 b = bp[kc * 256];
            uint4 a0 = ap0[kc * 32], a1 = ap1[kc * 32];
            uint4 a2 = ap2[kc * 32], a3 = ap3[kc * 32];
            mma16(acc2[0][0], a0, b.x, b.y);  mma16(acc2[0][1], a0, b.z, b.w);
            mma16(acc2[1][0], a1, b.x, b.y);  mma16(acc2[1][1], a1, b.z, b.w);
            mma16(acc2[2][0], a2, b.x, b.y);  mma16(acc2[2][1], a2, b.z, b.w);
            mma16(acc2[3][0], a3, b.x, b.y);  mma16(acc2[3][1], a3, b.z, b.w);
        }
    }
    __syncthreads();   // region reused as fp32 D2 staging [128][132]

    // ---- epilogue2: stage D2+bias, then red.v4 scatter ----
#pragma unroll
    for (int mi = 0; mi < 4; mi++)
#pragma unroll
        for (int nf = 0; nf < 2; nf++)
#pragma unroll
            for (int j = 0; j < 4; j++) {
                int m = wm * 64 + mi * 16 + (lane >> 2) + ((j >> 1) << 3);
                int n = wn * 16 + nf * 8 + ((lane & 3) << 1) + (j & 1);
                sAf[m * 132 + n] = acc2[mi][nf][j] + s_b2[n];
            }
    __syncthreads();
    {
        const int cc = tid & 31;
        const int r0 = tid >> 5;
#pragma unroll
        for (int it = 0; it < 8; it++) {
            int r = r0 + it * 16;
            float4 v = *(const float4*)(sAf + r * 132 + cc * 4);
            red4(agg + (size_t)s_dst[r] * DD + cc * 4, v);
        }
    }
}

// ---------------- fp16 tensor-core update MLP (residual) ---------------------
// CTA: 128 nodes, 512 threads = 16 warps (2M x 8N). K=256 both GEMMs.
__global__ void __launch_bounds__(512, 1) upd_mma_k(
    float* __restrict__ h, const float* __restrict__ agg,
    const unsigned int* __restrict__ W1f, const float* __restrict__ b1,
    const unsigned int* __restrict__ W2f, const float* __restrict__ b2)
{
    extern __shared__ __align__(16) unsigned int sAu[];   // 69632 B
    float* sAf = (float*)sAu;
    __shared__ float s_b1[HH];
    __shared__ float s_b2[DD];

    const int tid = threadIdx.x;
    const int n0 = blockIdx.x * 128;

    if (tid < HH) s_b1[tid] = b1[tid];
    if (tid < DD) s_b2[tid] = b2[tid];

    {
        const int e = tid >> 2, q = tid & 3;
        const float* hs = h + (size_t)(n0 + e) * DD;
        const float* ag = agg + (size_t)(n0 + e) * DD;
        const int r = e & 15, mt = e >> 4;
#pragma unroll
        for (int j = 0; j < 16; j++) {
            int k0 = j * 16 + q * 4;
            float4 v = (k0 < 128) ? *(const float4*)(hs + k0)
                                  : *(const float4*)(ag + (k0 - 128));
            stage_f4(sAu, 16, mt, r, k0, v);
        }
    }
    __syncthreads();

    const int wid = tid >> 5, lane = tid & 31;
    const int wm = wid >> 3, wn = wid & 7;

    float acc[4][4][4];
#pragma unroll
    for (int a = 0; a < 4; a++)
#pragma unroll
        for (int b = 0; b < 4; b++)
#pragma unroll
            for (int c = 0; c < 4; c++) acc[a][b][c] = 0.0f;
    {
        const uint4* ap0 = (const uint4*)sAu + (wm * 4 + 0) * 16 * 32 + lane;
        const uint4* ap1 = (const uint4*)sAu + (wm * 4 + 1) * 16 * 32 + lane;
        const uint4* ap2 = (const uint4*)sAu + (wm * 4 + 2) * 16 * 32 + lane;
        const uint4* ap3 = (const uint4*)sAu + (wm * 4 + 3) * 16 * 32 + lane;
        const uint4* bp = (const uint4*)W1f + (wn * 2) * 32 + lane;
#pragma unroll 2
        for (int kc = 0; kc < 16; kc++) {
            uint4 b0 = bp[kc * 512];
            uint4 b1v = bp[kc * 512 + 32];
            uint4 a0 = ap0[kc * 32], a1 = ap1[kc * 32];
            uint4 a2 = ap2[kc * 32], a3 = ap3[kc * 32];
            mma16(acc[0][0], a0, b0.x, b0.y);  mma16(acc[0][1], a0, b0.z, b0.w);
            mma16(acc[0][2], a0, b1v.x, b1v.y); mma16(acc[0][3], a0, b1v.z, b1v.w);
            mma16(acc[1][0], a1, b0.x, b0.y);  mma16(acc[1][1], a1, b0.z, b0.w);
            mma16(acc[1][2], a1, b1v.x, b1v.y); mma16(acc[1][3], a1, b1v.z, b1v.w);
            mma16(acc[2][0], a2, b0.x, b0.y);  mma16(acc[2][1], a2, b0.z, b0.w);
            mma16(acc[2][2], a2, b1v.x, b1v.y); mma16(acc[2][3], a2, b1v.z, b1v.w);
            mma16(acc[3][0], a3, b0.x, b0.y);  mma16(acc[3][1], a3, b0.z, b0.w);
            mma16(acc[3][2], a3, b1v.x, b1v.y); mma16(acc[3][3], a3, b1v.z, b1v.w);
        }
    }
    __syncthreads();

#pragma unroll
    for (int mi = 0; mi < 4; mi++)
#pragma unroll
        for (int nf = 0; nf < 4; nf++) {
            int m_lo = wm * 64 + mi * 16 + (lane >> 2);
            int n = wn * 32 + nf * 8 + ((lane & 3) << 1);
            float y00 = silu_f(acc[mi][nf][0] + s_b1[n]);
            float y01 = silu_f(acc[mi][nf][1] + s_b1[n + 1]);
            float y10 = silu_f(acc[mi][nf][2] + s_b1[n]);
            float y11 = silu_f(acc[mi][nf][3] + s_b1[n + 1]);
            int mt2 = m_lo >> 4;
            int kc2 = n >> 4, c2 = n & 15;
            int t2 = ((m_lo & 7) << 2) + ((c2 & 7) >> 1);
            int ib = (c2 & 8) ? 2 : 0;
            unsigned int* base = sAu + ((mt2 * 16 + kc2) * 32 + t2) * 4 + ib;
            base[0] = packh2(y00, y01);
            base[1] = packh2(y10, y11);
        }
    __syncthreads();

    float acc2[4][2][4];
#pragma unroll
    for (int a = 0; a < 4; a++)
#pragma unroll
        for (int b = 0; b < 2; b++)
#pragma unroll
            for (int c = 0; c < 4; c++) acc2[a][b][c] = 0.0f;
    {
        const uint4* ap0 = (const uint4*)sAu + (wm * 4 + 0) * 16 * 32 + lane;
        const uint4* ap1 = (const uint4*)sAu + (wm * 4 + 1) * 16 * 32 + lane;
        const uint4* ap2 = (const uint4*)sAu + (wm * 4 + 2) * 16 * 32 + lane;
        const uint4* ap3 = (const uint4*)sAu + (wm * 4 + 3) * 16 * 32 + lane;
        const uint4* bp = (const uint4*)W2f + wn * 32 + lane;
#pragma unroll 2
        for (int kc = 0; kc < 16; kc++) {
            uint4 b = bp[kc * 256];
            uint4 a0 = ap0[kc * 32], a1 = ap1[kc * 32];
            uint4 a2 = ap2[kc * 32], a3 = ap3[kc * 32];
            mma16(acc2[0][0], a0, b.x, b.y);  mma16(acc2[0][1], a0, b.z, b.w);
            mma16(acc2[1][0], a1, b.x, b.y);  mma16(acc2[1][1], a1, b.z, b.w);
            mma16(acc2[2][0], a2, b.x, b.y);  mma16(acc2[2][1], a2, b.z, b.w);
            mma16(acc2[3][0], a3, b.x, b.y);  mma16(acc2[3][1], a3, b.z, b.w);
        }
    }
    __syncthreads();

#pragma unroll
    for (int mi = 0; mi < 4; mi++)
#pragma unroll
        for (int nf = 0; nf < 2; nf++)
#pragma unroll
            for (int j = 0; j < 4; j++) {
                int m = wm * 64 + mi * 16 + (lane >> 2) + ((j >> 1) << 3);
                int n = wn * 16 + nf * 8 + ((lane & 3) << 1) + (j & 1);
                sAf[m * 132 + n] = acc2[mi][nf][j] + s_b2[n];
            }
    __syncthreads();
    {
        const int cc = tid & 31;
        const int r0 = tid >> 5;
#pragma unroll
        for (int it = 0; it < 8; it++) {
            int r = r0 + it * 16;
            float4 v = *(const float4*)(sAf + r * 132 + cc * 4);
            float* hp = h + (size_t)(n0 + r) * DD + cc * 4;
            float4 o = *(float4*)hp;
            o.x += v.x; o.y += v.y; o.z += v.z; o.w += v.w;
            *(float4*)hp = o;
        }
    }
}

// ---------------- per-graph counts ------------------------------------------
__global__ void cnt_k(const int* __restrict__ batch, float* __restrict__ cnt)
{
    int n = blockIdx.x * blockDim.x + threadIdx.x;
    if (n < NN) atomicAdd(&cnt[batch[n]], 1.0f);
}

// ---------------- per-graph feature sums ------------------------------------
__global__ void __launch_bounds__(128) gsum_k(
    const float* __restrict__ h, const int* __restrict__ batch,
    float* __restrict__ gsum)
{
    const int j = threadIdx.x;
    const int n0 = blockIdx.x * 32;
    int curb = batch[n0];
    float acc = 0.0f;
    for (int i = 0; i < 32; i++) {
        int n = n0 + i;
        int b = batch[n];
        if (b != curb) {
            atomicAdd(&gsum[curb * DD + j], acc);
            acc = 0.0f;
            curb = b;
        }
        acc += h[n * DD + j];
    }
    atomicAdd(&gsum[curb * DD + j], acc);
}

// ---------------- readout MLP (single block) --------------------------------
__global__ void __launch_bounds__(256) final_k(
    const float* __restrict__ gsum, const float* __restrict__ cnt,
    const float* __restrict__ W1, const float* __restrict__ b1,
    const float* __restrict__ W2, const float* __restrict__ b2,
    float* __restrict__ out)
{
    __shared__ float sg[BB * DD];
    __shared__ float sh[BB * HH];
    const int tid = threadIdx.x;

    for (int idx = tid; idx < BB * DD; idx += 256) {
        int b = idx >> 7;
        sg[idx] = gsum[idx] / fmaxf(cnt[b], 1.0f);
    }
    __syncthreads();

    {
        const int j = tid;
        float acc[BB];
#pragma unroll
        for (int b = 0; b < BB; b++) acc[b] = 0.0f;
        for (int k = 0; k < DD; k++) {
            float w = W1[k * HH + j];
#pragma unroll
            for (int b = 0; b < BB; b++) acc[b] = fmaf(sg[b * DD + k], w, acc[b]);
        }
        float bb = b1[j];
#pragma unroll
        for (int b = 0; b < BB; b++) sh[b * HH + j] = silu_f(acc[b] + bb);
    }
    __syncthreads();

    if (tid < OUTD) {
        const int j = tid;
        float acc[BB];
#pragma unroll
        for (int b = 0; b < BB; b++) acc[b] = 0.0f;
        for (int k = 0; k < HH; k++) {
            float w = W2[k * OUTD + j];
#pragma unroll
            for (int b = 0; b < BB; b++) acc[b] = fmaf(sh[b * HH + k], w, acc[b]);
        }
        float bb = b2[j];
#pragma unroll
        for (int b = 0; b < BB; b++) out[b * OUTD + j] = acc[b] + bb;
    }
}

// ---------------- launch -----------------------------------------------------
#define SMEM_MSG (8 * KC1H * 32 * 4 * 4)   // 69632 bytes (>= 67584 D2 staging)
#define SMEM_UPD (8 * 16 * 32 * 4 * 4)     // 65536 bytes (D2 staging 67584 <= 69632? use 69632)
#define SMEM_UPD_REAL 69632

extern "C" void kernel_launch(void* const* d_in, const int* in_sizes, int n_in,
                              void* d_out, int out_size)
{
    const float* pos    = (const float*)d_in[0];
    const float* nf     = (const float*)d_in[1];
    const int*   EI     = (const int*)d_in[2];
    const int*   batch  = (const int*)d_in[3];
    const float* emb_W1 = (const float*)d_in[4];
    const float* emb_b1 = (const float*)d_in[5];
    const float* emb_W2 = (const float*)d_in[6];
    const float* emb_b2 = (const float*)d_in[7];
    const float* msg_W1 = (const float*)d_in[8];
    const float* msg_b1 = (const float*)d_in[9];
    const float* msg_W2 = (const float*)d_in[10];
    const float* msg_b2 = (const float*)d_in[11];
    const float* upd_W1 = (const float*)d_in[12];
    const float* upd_b1 = (const float*)d_in[13];
    const float* upd_W2 = (const float*)d_in[14];
    const float* upd_b2 = (const float*)d_in[15];
    const float* r_W1   = (const float*)d_in[16];
    const float* r_b1   = (const float*)d_in[17];
    const float* r_W2   = (const float*)d_in[18];
    const float* r_b2   = (const float*)d_in[19];
    float* out = (float*)d_out;

    void *p_h, *p_agg, *p_gsum, *p_gcnt, *p_w1f, *p_w2f, *p_wu1f, *p_wu2f;
    cudaGetSymbolAddress(&p_h, g_h);
    cudaGetSymbolAddress(&p_agg, g_agg);
    cudaGetSymbolAddress(&p_gsum, g_gsum);
    cudaGetSymbolAddress(&p_gcnt, g_gcnt);
    cudaGetSymbolAddress(&p_w1f, g_W1f);
    cudaGetSymbolAddress(&p_w2f, g_W2f);
    cudaGetSymbolAddress(&p_wu1f, g_WU1f);
    cudaGetSymbolAddress(&p_wu2f, g_WU2f);
    float* h    = (float*)p_h;
    float* agg  = (float*)p_agg;
    float* gsum = (float*)p_gsum;
    float* gcnt = (float*)p_gcnt;
    unsigned int* W1f  = (unsigned int*)p_w1f;
    unsigned int* W2f  = (unsigned int*)p_w2f;
    unsigned int* WU1f = (unsigned int*)p_wu1f;
    unsigned int* WU2f = (unsigned int*)p_wu2f;

    cudaFuncSetAttribute(msg_mma_k, cudaFuncAttributeMaxDynamicSharedMemorySize, SMEM_MSG);
    cudaFuncSetAttribute(upd_mma_k, cudaFuncAttributeMaxDynamicSharedMemorySize, SMEM_UPD_REAL);

    prep1_k<<<(NL * KC1H * 16 * 32 * 4 + 255) / 256, 256>>>(msg_W1, W1f);
    prep2_k<<<(NL * KC2H * 8 * 32 * 4 + 255) / 256, 256>>>(msg_W2, W2f);
    prepU1_k<<<(NL * 16 * 16 * 32 * 4 + 255) / 256, 256>>>(upd_W1, WU1f);
    prepU2_k<<<(NL * 16 * 8 * 32 * 4 + 255) / 256, 256>>>(upd_W2, WU2f);
    embed_k<<<NN / 16, 128>>>(nf, emb_W1, emb_b1, emb_W2, emb_b2, h);

    for (int l = 0; l < NL; l++) {
        cudaMemsetAsync(agg, 0, (size_t)NN * DD * sizeof(float), 0);
        msg_mma_k<<<EE / 128, 512, SMEM_MSG>>>(
            EI, pos, h,
            W1f + (size_t)l * KC1H * 16 * 32 * 4,
            msg_b1 + (size_t)l * HH,
            W2f + (size_t)l * KC2H * 8 * 32 * 4,
            msg_b2 + (size_t)l * DD,
            agg);
        upd_mma_k<<<NN / 128, 512, SMEM_UPD_REAL>>>(
            h, agg,
            WU1f + (size_t)l * 16 * 16 * 32 * 4,
            upd_b1 + (size_t)l * HH,
            WU2f + (size_t)l * 16 * 8 * 32 * 4,
            upd_b2 + (size_t)l * DD);
    }

    cudaMemsetAsync(gsum, 0, (size_t)BB * DD * sizeof(float), 0);
    cudaMemsetAsync(gcnt, 0, (size_t)BB * sizeof(float), 0);
    cnt_k<<<NN / 256, 256>>>(batch, gcnt);
    gsum_k<<<NN / 32, 128>>>(h, batch, gsum);
    final_k<<<1, 256>>>(gsum, gcnt, r_W1, r_b1, r_W2, r_b2, out);
}

// round 14
// speedup vs baseline: 1.7701x; 1.0155x over previous
#include <cuda_runtime.h>
#include <cuda_fp16.h>
#include <math.h>
#include <stdint.h>

#define NN    16384
#define EE    524288
#define BB    8
#define FIN   26
#define DD    128
#define HH    256
#define OUTD  64
#define NL    4
#define NRBF  16
#define KIN   272          // 2*DD + NRBF = exactly 17 chunks of 16
#define KC1H  17           // msg GEMM1 k-chunks of 16 (no padding; kc16 = ef)
#define KC2H  16           // msg GEMM2 / upd k-chunks of 16 (K = 256)

// ---------------- scratch (device globals; no allocation allowed) ----------
__device__ float g_h[NN * DD];
__device__ float g_agg[NN * DD];
__device__ float g_gsum[BB * DD];
__device__ float g_gcnt[BB];
// weights in fp16 B-fragment layout (packed half2 per uint)
__device__ unsigned int g_W1f[NL * KC1H * 16 * 32 * 4];   // msg GEMM1 [l][kc][np16][t32][i4]
__device__ unsigned int g_W2f[NL * KC2H * 8 * 32 * 4];    // msg GEMM2
__device__ unsigned int g_WU1f[NL * 16 * 16 * 32 * 4];    // upd GEMM1
__device__ unsigned int g_WU2f[NL * 16 * 8 * 32 * 4];     // upd GEMM2

__device__ __forceinline__ float silu_f(float x) {
    return x * (1.0f / (1.0f + __expf(-x)));
}
__device__ __forceinline__ unsigned int packh2(float a, float b) {
    __half2 h = __floats2half2_rn(a, b);
    return *reinterpret_cast<unsigned int*>(&h);
}

// fp16 m16n8k16 MMA (baseline PTX, valid on compute_103)
__device__ __forceinline__ void mma16(float* c, uint4 a, uint32_t b0, uint32_t b1) {
    asm volatile(
        "mma.sync.aligned.m16n8k16.row.col.f32.f16.f16.f32 "
        "{%0,%1,%2,%3}, {%4,%5,%6,%7}, {%8,%9}, {%0,%1,%2,%3};"
        : "+f"(c[0]), "+f"(c[1]), "+f"(c[2]), "+f"(c[3])
        : "r"(a.x), "r"(a.y), "r"(a.z), "r"(a.w), "r"(b0), "r"(b1));
}

__device__ __forceinline__ void red4(float* p, float4 v) {
    asm volatile("red.global.add.v4.f32 [%0], {%1,%2,%3,%4};"
                 :: "l"(p), "f"(v.x), "f"(v.y), "f"(v.z), "f"(v.w) : "memory");
}

// ---------------- weight prep: fp16 fragment layout --------------------------
__global__ void prep1_k(const float* __restrict__ W1, unsigned int* __restrict__ Wf) {
    int idx = blockIdx.x * 256 + threadIdx.x;
    const int PER = KC1H * 16 * 32 * 4;
    if (idx >= NL * PER) return;
    int l = idx / PER, r = idx - l * PER;
    int kc = r / 2048;  r -= kc * 2048;
    int np = r / 128;   r -= np * 128;
    int t = r / 4, i = r & 3;
    int k0 = kc * 16 + (t & 3) * 2 + 8 * (i & 1);
    int n = np * 16 + ((i >> 1) << 3) + (t >> 2);
    float v0 = (k0 < KIN)     ? W1[((size_t)l * KIN + k0) * HH + n]     : 0.0f;
    float v1 = (k0 + 1 < KIN) ? W1[((size_t)l * KIN + k0 + 1) * HH + n] : 0.0f;
    Wf[idx] = packh2(v0, v1);
}
__global__ void prep2_k(const float* __restrict__ W2, unsigned int* __restrict__ Wf) {
    int idx = blockIdx.x * 256 + threadIdx.x;
    const int PER = KC2H * 8 * 32 * 4;
    if (idx >= NL * PER) return;
    int l = idx / PER, r = idx - l * PER;
    int kc = r / 1024;  r -= kc * 1024;
    int np = r / 128;   r -= np * 128;
    int t = r / 4, i = r & 3;
    int k0 = kc * 16 + (t & 3) * 2 + 8 * (i & 1);
    int n = np * 16 + ((i >> 1) << 3) + (t >> 2);
    Wf[idx] = packh2(W2[((size_t)l * HH + k0) * DD + n],
                     W2[((size_t)l * HH + k0 + 1) * DD + n]);
}
__global__ void prepU1_k(const float* __restrict__ W1, unsigned int* __restrict__ Wf) {
    int idx = blockIdx.x * 256 + threadIdx.x;
    const int PER = 16 * 16 * 32 * 4;
    if (idx >= NL * PER) return;
    int l = idx / PER, r = idx - l * PER;
    int kc = r / 2048;  r -= kc * 2048;
    int np = r / 128;   r -= np * 128;
    int t = r / 4, i = r & 3;
    int k0 = kc * 16 + (t & 3) * 2 + 8 * (i & 1);
    int n = np * 16 + ((i >> 1) << 3) + (t >> 2);
    Wf[idx] = packh2(W1[((size_t)l * 256 + k0) * HH + n],
                     W1[((size_t)l * 256 + k0 + 1) * HH + n]);
}
__global__ void prepU2_k(const float* __restrict__ W2, unsigned int* __restrict__ Wf) {
    int idx = blockIdx.x * 256 + threadIdx.x;
    const int PER = 16 * 8 * 32 * 4;
    if (idx >= NL * PER) return;
    int l = idx / PER, r = idx - l * PER;
    int kc = r / 1024;  r -= kc * 1024;
    int np = r / 128;   r -= np * 128;
    int t = r / 4, i = r & 3;
    int k0 = kc * 16 + (t & 3) * 2 + 8 * (i & 1);
    int n = np * 16 + ((i >> 1) << 3) + (t >> 2);
    Wf[idx] = packh2(W2[((size_t)l * HH + k0) * DD + n],
                     W2[((size_t)l * HH + k0 + 1) * DD + n]);
}

// ---------------- node embedding: (N,26) -> silu -> (N,128), fp32 ------------
__global__ void __launch_bounds__(128) embed_k(
    const float* __restrict__ nf,
    const float* __restrict__ W1, const float* __restrict__ b1,
    const float* __restrict__ W2, const float* __restrict__ b2,
    float* __restrict__ h)
{
    __shared__ __align__(16) float s_in[16 * FIN];
    __shared__ __align__(16) float s_hid[16 * DD];
    const int tid = threadIdx.x;
    const int n0 = blockIdx.x * 16;

    for (int idx = tid; idx < 16 * FIN; idx += 128) {
        int e = idx / FIN, k = idx - e * FIN;
        s_in[idx] = nf[(n0 + e) * FIN + k];
    }
    __syncthreads();

    const int j = tid;
    float acc[16];
#pragma unroll
    for (int e = 0; e < 16; e++) acc[e] = 0.0f;
    for (int k = 0; k < FIN; k++) {
        float w = W1[k * DD + j];
#pragma unroll
        for (int e = 0; e < 16; e++) acc[e] = fmaf(s_in[e * FIN + k], w, acc[e]);
    }
    float bb1 = b1[j];
#pragma unroll
    for (int e = 0; e < 16; e++) s_hid[e * DD + j] = silu_f(acc[e] + bb1);
    __syncthreads();

    float acc2[16];
#pragma unroll
    for (int e = 0; e < 16; e++) acc2[e] = 0.0f;
    const float4* sh4 = (const float4*)s_hid;
    for (int k4 = 0; k4 < DD / 4; k4++) {
        const float* wp = &W2[(k4 * 4) * DD + j];
        float w0 = wp[0], w1 = wp[DD], w2 = wp[2 * DD], w3 = wp[3 * DD];
#pragma unroll
        for (int e = 0; e < 16; e++) {
            float4 a = sh4[e * (DD / 4) + k4];
            acc2[e] = fmaf(a.x, w0, acc2[e]);
            acc2[e] = fmaf(a.y, w1, acc2[e]);
            acc2[e] = fmaf(a.z, w2, acc2[e]);
            acc2[e] = fmaf(a.w, w3, acc2[e]);
        }
    }
    float bb2 = b2[j];
#pragma unroll
    for (int e = 0; e < 16; e++) h[(n0 + e) * DD + j] = acc2[e] + bb2;
}

// ---------------- fp16 A-fragment staging helper -----------------------------
__device__ __forceinline__ void stage_f4(unsigned int* sAu, int KC, int mt, int r,
                                         int k0, float4 v) {
    int kc = k0 >> 4;
    int c0 = k0 & 15;
    int t0 = ((r & 7) << 2) + ((c0 & 7) >> 1);
    int ii = (r >> 3) + ((c0 & 8) ? 2 : 0);
    unsigned int* base = sAu + ((mt * KC + kc) * 32) * 4 + ii;
    base[t0 * 4]       = packh2(v.x, v.y);
    base[(t0 + 1) * 4] = packh2(v.z, v.w);
}

// ---------------- fp16 tensor-core message MLP + v4-red scatter --------------
// CTA: 128 edges, 512 threads = 16 warps.
// GEMM1: 1M x 16N warp grid (each warp: all 8 M-tiles, one 16-wide N-slice;
//        B fragments read from L2 exactly ONCE per CTA).
// GEMM2: 2M x 8N (unchanged).
__global__ void __launch_bounds__(512, 1) msg_mma_k(
    const int* __restrict__ EI, const float* __restrict__ pos,
    const float* __restrict__ h,
    const unsigned int* __restrict__ W1f, const float* __restrict__ b1,
    const unsigned int* __restrict__ W2f, const float* __restrict__ b2,
    float* __restrict__ agg)
{
    extern __shared__ __align__(16) unsigned int sAu[];   // 69632 B (KC1H layout)
    float* sAf = (float*)sAu;
    __shared__ float s_b1[HH];
    __shared__ float s_b2[DD];
    __shared__ int   s_dst[128];

    const int tid = threadIdx.x;
    const int e0 = blockIdx.x * 128;

    if (tid < HH) s_b1[tid] = b1[tid];
    if (tid < DD) s_b2[tid] = b2[tid];
    if (tid < 128) s_dst[tid] = EI[EE + e0 + tid];

    // ---- stage gathered edge features into fp16 A-fragment layout ----
    {
        const int e = tid >> 2;
        const int q = tid & 3;
        const int src = EI[e0 + e];
        const int dst = EI[EE + e0 + e];
        const float* hs = h + (size_t)src * DD;
        const float* hd = h + (size_t)dst * DD;
        const int r = e & 15, mt = e >> 4;
#pragma unroll
        for (int j = 0; j < 16; j++) {
            int k0 = j * 16 + q * 4;
            float4 v = (k0 < 128) ? *(const float4*)(hs + k0)
                                  : *(const float4*)(hd + (k0 - 128));
            stage_f4(sAu, KC1H, mt, r, k0, v);
        }
        // chunk kc=16: RBF features (4 values per staging thread)
        float dx = pos[dst * 3 + 0] - pos[src * 3 + 0];
        float dy = pos[dst * 3 + 1] - pos[src * 3 + 1];
        float dz = pos[dst * 3 + 2] - pos[src * 3 + 2];
        float dist = sqrtf(dx * dx + dy * dy + dz * dz + 1e-12f);
        float env = (dist < 10.0f)
                        ? 0.5f * (cosf(3.14159265358979323846f * dist * 0.1f) + 1.0f)
                        : 0.0f;
        const float inv2w2 = 1.0f / (2.0f * 0.625f * 0.625f);
        float rv[4];
#pragma unroll
        for (int kk = 0; kk < 4; kk++) {
            float c = (10.0f / 15.0f) * (float)(q * 4 + kk);
            float t = dist - c;
            rv[kk] = __expf(-t * t * inv2w2) * env;
        }
        stage_f4(sAu, KC1H, mt, r, 256 + q * 4,
                 make_float4(rv[0], rv[1], rv[2], rv[3]));
    }
    __syncthreads();

    const int wid = tid >> 5, lane = tid & 31;

    // ================= GEMM1: 1M x 16N, acc[8 mtiles][2 nfrags] =============
    float acc[8][2][4];
#pragma unroll
    for (int a = 0; a < 8; a++)
#pragma unroll
        for (int b = 0; b < 2; b++)
#pragma unroll
            for (int c = 0; c < 4; c++) acc[a][b][c] = 0.0f;
    {
        const uint4* ap = (const uint4*)sAu + lane;
        const uint4* bp = (const uint4*)W1f + wid * 32 + lane;
#pragma unroll 1
        for (int kc = 0; kc < KC1H; kc++) {
            uint4 b = bp[kc * 512];
#pragma unroll
            for (int mi = 0; mi < 8; mi++) {
                uint4 a = ap[(mi * KC1H + kc) * 32];
                mma16(acc[mi][0], a, b.x, b.y);
                mma16(acc[mi][1], a, b.z, b.w);
            }
        }
    }
    __syncthreads();

    // ---- epilogue1: bias + silu -> A2 fp16 fragment layout (KC2H) ----
#pragma unroll
    for (int mi = 0; mi < 8; mi++)
#pragma unroll
        for (int nf = 0; nf < 2; nf++) {
            int m_lo = mi * 16 + (lane >> 2);
            int n = wid * 16 + nf * 8 + ((lane & 3) << 1);
            float y00 = silu_f(acc[mi][nf][0] + s_b1[n]);
            float y01 = silu_f(acc[mi][nf][1] + s_b1[n + 1]);
            float y10 = silu_f(acc[mi][nf][2] + s_b1[n]);
            float y11 = silu_f(acc[mi][nf][3] + s_b1[n + 1]);
            int kc2 = n >> 4, c2 = n & 15;
            int t2 = ((m_lo & 7) << 2) + ((c2 & 7) >> 1);
            int ib = (c2 & 8) ? 2 : 0;
            unsigned int* base = sAu + ((mi * KC2H + kc2) * 32 + t2) * 4 + ib;
            base[0] = packh2(y00, y01);
            base[1] = packh2(y10, y11);
        }
    __syncthreads();

    // ================= GEMM2: 2M x 8N (unchanged) ===========================
    const int wm = wid >> 3, wn = wid & 7;
    float acc2[4][2][4];
#pragma unroll
    for (int a = 0; a < 4; a++)
#pragma unroll
        for (int b = 0; b < 2; b++)
#pragma unroll
            for (int c = 0; c < 4; c++) acc2[a][b][c] = 0.0f;
    {
        const uint4* ap0 = (const uint4*)sAu + (wm * 4 + 0) * KC2H * 32 + lane;
        const uint4* ap1 = (const uint4*)sAu + (wm * 4 + 1) * KC2H * 32 + lane;
        const uint4* ap2 = (const uint4*)sAu + (wm * 4 + 2) * KC2H * 32 + lane;
        const uint4* ap3 = (const uint4*)sAu + (wm * 4 + 3) * KC2H * 32 + lane;
        const uint4* bp = (const uint4*)W2f + wn * 32 + lane;
#pragma unroll 2
        for (int kc = 0; kc < KC2H; kc++) {
            uint4 b = bp[kc * 256];
            uint4 a0 = ap0[kc * 32], a1 = ap1[kc * 32];
            uint4 a2 = ap2[kc * 32], a3 = ap3[kc * 32];
            mma16(acc2[0][0], a0, b.x, b.y);  mma16(acc2[0][1], a0, b.z, b.w);
            mma16(acc2[1][0], a1, b.x, b.y);  mma16(acc2[1][1], a1, b.z, b.w);
            mma16(acc2[2][0], a2, b.x, b.y);  mma16(acc2[2][1], a2, b.z, b.w);
            mma16(acc2[3][0], a3, b.x, b.y);  mma16(acc2[3][1], a3, b.z, b.w);
        }
    }
    __syncthreads();   // region reused as fp32 D2 staging [128][132]

    // ---- epilogue2: stage D2+bias, then red.v4 scatter ----
#pragma unroll
    for (int mi = 0; mi < 4; mi++)
#pragma unroll
        for (int nf = 0; nf < 2; nf++)
#pragma unroll
            for (int j = 0; j < 4; j++) {
                int m = wm * 64 + mi * 16 + (lane >> 2) + ((j >> 1) << 3);
                int n = wn * 16 + nf * 8 + ((lane & 3) << 1) + (j & 1);
                sAf[m * 132 + n] = acc2[mi][nf][j] + s_b2[n];
            }
    __syncthreads();
    {
        const int cc = tid & 31;
        const int r0 = tid >> 5;
#pragma unroll
        for (int it = 0; it < 8; it++) {
            int r = r0 + it * 16;
            float4 v = *(const float4*)(sAf + r * 132 + cc * 4);
            red4(agg + (size_t)s_dst[r] * DD + cc * 4, v);
        }
    }
}

// ---------------- fp16 tensor-core update MLP (residual) ---------------------
// CTA: 128 nodes, 512 threads. GEMM1: 1M x 16N; GEMM2: 2M x 8N.
__global__ void __launch_bounds__(512, 1) upd_mma_k(
    float* __restrict__ h, const float* __restrict__ agg,
    const unsigned int* __restrict__ W1f, const float* __restrict__ b1,
    const unsigned int* __restrict__ W2f, const float* __restrict__ b2)
{
    extern __shared__ __align__(16) unsigned int sAu[];   // 69632 B
    float* sAf = (float*)sAu;
    __shared__ float s_b1[HH];
    __shared__ float s_b2[DD];

    const int tid = threadIdx.x;
    const int n0 = blockIdx.x * 128;

    if (tid < HH) s_b1[tid] = b1[tid];
    if (tid < DD) s_b2[tid] = b2[tid];

    {
        const int e = tid >> 2, q = tid & 3;
        const float* hs = h + (size_t)(n0 + e) * DD;
        const float* ag = agg + (size_t)(n0 + e) * DD;
        const int r = e & 15, mt = e >> 4;
#pragma unroll
        for (int j = 0; j < 16; j++) {
            int k0 = j * 16 + q * 4;
            float4 v = (k0 < 128) ? *(const float4*)(hs + k0)
                                  : *(const float4*)(ag + (k0 - 128));
            stage_f4(sAu, 16, mt, r, k0, v);
        }
    }
    __syncthreads();

    const int wid = tid >> 5, lane = tid & 31;

    // GEMM1: 1M x 16N
    float acc[8][2][4];
#pragma unroll
    for (int a = 0; a < 8; a++)
#pragma unroll
        for (int b = 0; b < 2; b++)
#pragma unroll
            for (int c = 0; c < 4; c++) acc[a][b][c] = 0.0f;
    {
        const uint4* ap = (const uint4*)sAu + lane;
        const uint4* bp = (const uint4*)W1f + wid * 32 + lane;
#pragma unroll 1
        for (int kc = 0; kc < 16; kc++) {
            uint4 b = bp[kc * 512];
#pragma unroll
            for (int mi = 0; mi < 8; mi++) {
                uint4 a = ap[(mi * 16 + kc) * 32];
                mma16(acc[mi][0], a, b.x, b.y);
                mma16(acc[mi][1], a, b.z, b.w);
            }
        }
    }
    __syncthreads();

#pragma unroll
    for (int mi = 0; mi < 8; mi++)
#pragma unroll
        for (int nf = 0; nf < 2; nf++) {
            int m_lo = mi * 16 + (lane >> 2);
            int n = wid * 16 + nf * 8 + ((lane & 3) << 1);
            float y00 = silu_f(acc[mi][nf][0] + s_b1[n]);
            float y01 = silu_f(acc[mi][nf][1] + s_b1[n + 1]);
            float y10 = silu_f(acc[mi][nf][2] + s_b1[n]);
            float y11 = silu_f(acc[mi][nf][3] + s_b1[n + 1]);
            int kc2 = n >> 4, c2 = n & 15;
            int t2 = ((m_lo & 7) << 2) + ((c2 & 7) >> 1);
            int ib = (c2 & 8) ? 2 : 0;
            unsigned int* base = sAu + ((mi * 16 + kc2) * 32 + t2) * 4 + ib;
            base[0] = packh2(y00, y01);
            base[1] = packh2(y10, y11);
        }
    __syncthreads();

    // GEMM2: 2M x 8N
    const int wm = wid >> 3, wn = wid & 7;
    float acc2[4][2][4];
#pragma unroll
    for (int a = 0; a < 4; a++)
#pragma unroll
        for (int b = 0; b < 2; b++)
#pragma unroll
            for (int c = 0; c < 4; c++) acc2[a][b][c] = 0.0f;
    {
        const uint4* ap0 = (const uint4*)sAu + (wm * 4 + 0) * 16 * 32 + lane;
        const uint4* ap1 = (const uint4*)sAu + (wm * 4 + 1) * 16 * 32 + lane;
        const uint4* ap2 = (const uint4*)sAu + (wm * 4 + 2) * 16 * 32 + lane;
        const uint4* ap3 = (const uint4*)sAu + (wm * 4 + 3) * 16 * 32 + lane;
        const uint4* bp = (const uint4*)W2f + wn * 32 + lane;
#pragma unroll 2
        for (int kc = 0; kc < 16; kc++) {
            uint4 b = bp[kc * 256];
            uint4 a0 = ap0[kc * 32], a1 = ap1[kc * 32];
            uint4 a2 = ap2[kc * 32], a3 = ap3[kc * 32];
            mma16(acc2[0][0], a0, b.x, b.y);  mma16(acc2[0][1], a0, b.z, b.w);
            mma16(acc2[1][0], a1, b.x, b.y);  mma16(acc2[1][1], a1, b.z, b.w);
            mma16(acc2[2][0], a2, b.x, b.y);  mma16(acc2[2][1], a2, b.z, b.w);
            mma16(acc2[3][0], a3, b.x, b.y);  mma16(acc2[3][1], a3, b.z, b.w);
        }
    }
    __syncthreads();

#pragma unroll
    for (int mi = 0; mi < 4; mi++)
#pragma unroll
        for (int nf = 0; nf < 2; nf++)
#pragma unroll
            for (int j = 0; j < 4; j++) {
                int m = wm * 64 + mi * 16 + (lane >> 2) + ((j >> 1) << 3);
                int n = wn * 16 + nf * 8 + ((lane & 3) << 1) + (j & 1);
                sAf[m * 132 + n] = acc2[mi][nf][j] + s_b2[n];
            }
    __syncthreads();
    {
        const int cc = tid & 31;
        const int r0 = tid >> 5;
#pragma unroll
        for (int it = 0; it < 8; it++) {
            int r = r0 + it * 16;
            float4 v = *(const float4*)(sAf + r * 132 + cc * 4);
            float* hp = h + (size_t)(n0 + r) * DD + cc * 4;
            float4 o = *(float4*)hp;
            o.x += v.x; o.y += v.y; o.z += v.z; o.w += v.w;
            *(float4*)hp = o;
        }
    }
}

// ---------------- per-graph counts ------------------------------------------
__global__ void cnt_k(const int* __restrict__ batch, float* __restrict__ cnt)
{
    int n = blockIdx.x * blockDim.x + threadIdx.x;
    if (n < NN) atomicAdd(&cnt[batch[n]], 1.0f);
}

// ---------------- per-graph feature sums ------------------------------------
__global__ void __launch_bounds__(128) gsum_k(
    const float* __restrict__ h, const int* __restrict__ batch,
    float* __restrict__ gsum)
{
    const int j = threadIdx.x;
    const int n0 = blockIdx.x * 32;
    int curb = batch[n0];
    float acc = 0.0f;
    for (int i = 0; i < 32; i++) {
        int n = n0 + i;
        int b = batch[n];
        if (b != curb) {
            atomicAdd(&gsum[curb * DD + j], acc);
            acc = 0.0f;
            curb = b;
        }
        acc += h[n * DD + j];
    }
    atomicAdd(&gsum[curb * DD + j], acc);
}

// ---------------- readout MLP (single block) --------------------------------
__global__ void __launch_bounds__(256) final_k(
    const float* __restrict__ gsum, const float* __restrict__ cnt,
    const float* __restrict__ W1, const float* __restrict__ b1,
    const float* __restrict__ W2, const float* __restrict__ b2,
    float* __restrict__ out)
{
    __shared__ float sg[BB * DD];
    __shared__ float sh[BB * HH];
    const int tid = threadIdx.x;

    for (int idx = tid; idx < BB * DD; idx += 256) {
        int b = idx >> 7;
        sg[idx] = gsum[idx] / fmaxf(cnt[b], 1.0f);
    }
    __syncthreads();

    {
        const int j = tid;
        float acc[BB];
#pragma unroll
        for (int b = 0; b < BB; b++) acc[b] = 0.0f;
        for (int k = 0; k < DD; k++) {
            float w = W1[k * HH + j];
#pragma unroll
            for (int b = 0; b < BB; b++) acc[b] = fmaf(sg[b * DD + k], w, acc[b]);
        }
        float bb = b1[j];
#pragma unroll
        for (int b = 0; b < BB; b++) sh[b * HH + j] = silu_f(acc[b] + bb);
    }
    __syncthreads();

    if (tid < OUTD) {
        const int j = tid;
        float acc[BB];
#pragma unroll
        for (int b = 0; b < BB; b++) acc[b] = 0.0f;
        for (int k = 0; k < HH; k++) {
            float w = W2[k * OUTD + j];
#pragma unroll
            for (int b = 0; b < BB; b++) acc[b] = fmaf(sh[b * HH + k], w, acc[b]);
        }
        float bb = b2[j];
#pragma unroll
        for (int b = 0; b < BB; b++) out[b * OUTD + j] = acc[b] + bb;
    }
}

// ---------------- launch -----------------------------------------------------
#define SMEM_MSG (8 * KC1H * 32 * 4 * 4)   // 69632 bytes
#define SMEM_UPD 69632

extern "C" void kernel_launch(void* const* d_in, const int* in_sizes, int n_in,
                              void* d_out, int out_size)
{
    const float* pos    = (const float*)d_in[0];
    const float* nf     = (const float*)d_in[1];
    const int*   EI     = (const int*)d_in[2];
    const int*   batch  = (const int*)d_in[3];
    const float* emb_W1 = (const float*)d_in[4];
    const float* emb_b1 = (const float*)d_in[5];
    const float* emb_W2 = (const float*)d_in[6];
    const float* emb_b2 = (const float*)d_in[7];
    const float* msg_W1 = (const float*)d_in[8];
    const float* msg_b1 = (const float*)d_in[9];
    const float* msg_W2 = (const float*)d_in[10];
    const float* msg_b2 = (const float*)d_in[11];
    const float* upd_W1 = (const float*)d_in[12];
    const float* upd_b1 = (const float*)d_in[13];
    const float* upd_W2 = (const float*)d_in[14];
    const float* upd_b2 = (const float*)d_in[15];
    const float* r_W1   = (const float*)d_in[16];
    const float* r_b1   = (const float*)d_in[17];
    const float* r_W2   = (const float*)d_in[18];
    const float* r_b2   = (const float*)d_in[19];
    float* out = (float*)d_out;

    void *p_h, *p_agg, *p_gsum, *p_gcnt, *p_w1f, *p_w2f, *p_wu1f, *p_wu2f;
    cudaGetSymbolAddress(&p_h, g_h);
    cudaGetSymbolAddress(&p_agg, g_agg);
    cudaGetSymbolAddress(&p_gsum, g_gsum);
    cudaGetSymbolAddress(&p_gcnt, g_gcnt);
    cudaGetSymbolAddress(&p_w1f, g_W1f);
    cudaGetSymbolAddress(&p_w2f, g_W2f);
    cudaGetSymbolAddress(&p_wu1f, g_WU1f);
    cudaGetSymbolAddress(&p_wu2f, g_WU2f);
    float* h    = (float*)p_h;
    float* agg  = (float*)p_agg;
    float* gsum = (float*)p_gsum;
    float* gcnt = (float*)p_gcnt;
    unsigned int* W1f  = (unsigned int*)p_w1f;
    unsigned int* W2f  = (unsigned int*)p_w2f;
    unsigned int* WU1f = (unsigned int*)p_wu1f;
    unsigned int* WU2f = (unsigned int*)p_wu2f;

    cudaFuncSetAttribute(msg_mma_k, cudaFuncAttributeMaxDynamicSharedMemorySize, SMEM_MSG);
    cudaFuncSetAttribute(upd_mma_k, cudaFuncAttributeMaxDynamicSharedMemorySize, SMEM_UPD);

    prep1_k<<<(NL * KC1H * 16 * 32 * 4 + 255) / 256, 256>>>(msg_W1, W1f);
    prep2_k<<<(NL * KC2H * 8 * 32 * 4 + 255) / 256, 256>>>(msg_W2, W2f);
    prepU1_k<<<(NL * 16 * 16 * 32 * 4 + 255) / 256, 256>>>(upd_W1, WU1f);
    prepU2_k<<<(NL * 16 * 8 * 32 * 4 + 255) / 256, 256>>>(upd_W2, WU2f);
    embed_k<<<NN / 16, 128>>>(nf, emb_W1, emb_b1, emb_W2, emb_b2, h);

    for (int l = 0; l < NL; l++) {
        cudaMemsetAsync(agg, 0, (size_t)NN * DD * sizeof(float), 0);
        msg_mma_k<<<EE / 128, 512, SMEM_MSG>>>(
            EI, pos, h,
            W1f + (size_t)l * KC1H * 16 * 32 * 4,
            msg_b1 + (size_t)l * HH,
            W2f + (size_t)l * KC2H * 8 * 32 * 4,
            msg_b2 + (size_t)l * DD,
            agg);
        upd_mma_k<<<NN / 128, 512, SMEM_UPD>>>(
            h, agg,
            WU1f + (size_t)l * 16 * 16 * 32 * 4,
            upd_b1 + (size_t)l * HH,
            WU2f + (size_t)l * 16 * 8 * 32 * 4,
            upd_b2 + (size_t)l * DD);
    }

    cudaMemsetAsync(gsum, 0, (size_t)BB * DD * sizeof(float), 0);
    cudaMemsetAsync(gcnt, 0, (size_t)BB * sizeof(float), 0);
    cnt_k<<<NN / 256, 256>>>(batch, gcnt);
    gsum_k<<<NN / 32, 128>>>(h, batch, gsum);
    final_k<<<1, 256>>>(gsum, gcnt, r_W1, r_b1, r_W2, r_b2, out);
}

// round 15
// speedup vs baseline: 1.9830x; 1.1203x over previous
#include <cuda_runtime.h>
#include <cuda_fp16.h>
#include <math.h>
#include <stdint.h>

#define NN    16384
#define EE    524288
#define BB    8
#define FIN   26
#define DD    128
#define HH    256
#define OUTD  64
#define NL    4
#define NRBF  16
#define KIN   272          // 2*DD + NRBF = exactly 17 chunks of 16
#define KC1H  17           // msg GEMM1 k-chunks of 16 (no padding; kc16 = ef)
#define KC2H  16           // msg GEMM2 / upd k-chunks of 16 (K = 256)

// ---------------- scratch (device globals; no allocation allowed) ----------
__device__ float g_h[NN * DD];
__device__ float g_agg[NN * DD];
__device__ float g_gsum[BB * DD];
__device__ float g_gcnt[BB];
// weights in fp16 B-fragment layout (packed half2 per uint)
__device__ unsigned int g_W1f[NL * KC1H * 16 * 32 * 4];   // msg GEMM1 [l][kc][np16][t32][i4]
__device__ unsigned int g_W2f[NL * KC2H * 8 * 32 * 4];    // msg GEMM2
__device__ unsigned int g_WU1f[NL * 16 * 16 * 32 * 4];    // upd GEMM1
__device__ unsigned int g_WU2f[NL * 16 * 8 * 32 * 4];     // upd GEMM2

__device__ __forceinline__ float silu_f(float x) {
    return x * (1.0f / (1.0f + __expf(-x)));
}
__device__ __forceinline__ unsigned int packh2(float a, float b) {
    __half2 h = __floats2half2_rn(a, b);
    return *reinterpret_cast<unsigned int*>(&h);
}

// fp16 m16n8k16 MMA (baseline PTX, valid on compute_103)
__device__ __forceinline__ void mma16(float* c, uint4 a, uint32_t b0, uint32_t b1) {
    asm volatile(
        "mma.sync.aligned.m16n8k16.row.col.f32.f16.f16.f32 "
        "{%0,%1,%2,%3}, {%4,%5,%6,%7}, {%8,%9}, {%0,%1,%2,%3};"
        : "+f"(c[0]), "+f"(c[1]), "+f"(c[2]), "+f"(c[3])
        : "r"(a.x), "r"(a.y), "r"(a.z), "r"(a.w), "r"(b0), "r"(b1));
}

__device__ __forceinline__ void red4(float* p, float4 v) {
    asm volatile("red.global.add.v4.f32 [%0], {%1,%2,%3,%4};"
                 :: "l"(p), "f"(v.x), "f"(v.y), "f"(v.z), "f"(v.w) : "memory");
}

// ---------------- weight prep: fp16 fragment layout --------------------------
__global__ void prep1_k(const float* __restrict__ W1, unsigned int* __restrict__ Wf) {
    int idx = blockIdx.x * 256 + threadIdx.x;
    const int PER = KC1H * 16 * 32 * 4;
    if (idx >= NL * PER) return;
    int l = idx / PER, r = idx - l * PER;
    int kc = r / 2048;  r -= kc * 2048;
    int np = r / 128;   r -= np * 128;
    int t = r / 4, i = r & 3;
    int k0 = kc * 16 + (t & 3) * 2 + 8 * (i & 1);
    int n = np * 16 + ((i >> 1) << 3) + (t >> 2);
    float v0 = (k0 < KIN)     ? W1[((size_t)l * KIN + k0) * HH + n]     : 0.0f;
    float v1 = (k0 + 1 < KIN) ? W1[((size_t)l * KIN + k0 + 1) * HH + n] : 0.0f;
    Wf[idx] = packh2(v0, v1);
}
__global__ void prep2_k(const float* __restrict__ W2, unsigned int* __restrict__ Wf) {
    int idx = blockIdx.x * 256 + threadIdx.x;
    const int PER = KC2H * 8 * 32 * 4;
    if (idx >= NL * PER) return;
    int l = idx / PER, r = idx - l * PER;
    int kc = r / 1024;  r -= kc * 1024;
    int np = r / 128;   r -= np * 128;
    int t = r / 4, i = r & 3;
    int k0 = kc * 16 + (t & 3) * 2 + 8 * (i & 1);
    int n = np * 16 + ((i >> 1) << 3) + (t >> 2);
    Wf[idx] = packh2(W2[((size_t)l * HH + k0) * DD + n],
                     W2[((size_t)l * HH + k0 + 1) * DD + n]);
}
__global__ void prepU1_k(const float* __restrict__ W1, unsigned int* __restrict__ Wf) {
    int idx = blockIdx.x * 256 + threadIdx.x;
    const int PER = 16 * 16 * 32 * 4;
    if (idx >= NL * PER) return;
    int l = idx / PER, r = idx - l * PER;
    int kc = r / 2048;  r -= kc * 2048;
    int np = r / 128;   r -= np * 128;
    int t = r / 4, i = r & 3;
    int k0 = kc * 16 + (t & 3) * 2 + 8 * (i & 1);
    int n = np * 16 + ((i >> 1) << 3) + (t >> 2);
    Wf[idx] = packh2(W1[((size_t)l * 256 + k0) * HH + n],
                     W1[((size_t)l * 256 + k0 + 1) * HH + n]);
}
__global__ void prepU2_k(const float* __restrict__ W2, unsigned int* __restrict__ Wf) {
    int idx = blockIdx.x * 256 + threadIdx.x;
    const int PER = 16 * 8 * 32 * 4;
    if (idx >= NL * PER) return;
    int l = idx / PER, r = idx - l * PER;
    int kc = r / 1024;  r -= kc * 1024;
    int np = r / 128;   r -= np * 128;
    int t = r / 4, i = r & 3;
    int k0 = kc * 16 + (t & 3) * 2 + 8 * (i & 1);
    int n = np * 16 + ((i >> 1) << 3) + (t >> 2);
    Wf[idx] = packh2(W2[((size_t)l * HH + k0) * DD + n],
                     W2[((size_t)l * HH + k0 + 1) * DD + n]);
}

// ---------------- node embedding: (N,26) -> silu -> (N,128), fp32 ------------
__global__ void __launch_bounds__(128) embed_k(
    const float* __restrict__ nf,
    const float* __restrict__ W1, const float* __restrict__ b1,
    const float* __restrict__ W2, const float* __restrict__ b2,
    float* __restrict__ h)
{
    __shared__ __align__(16) float s_in[16 * FIN];
    __shared__ __align__(16) float s_hid[16 * DD];
    const int tid = threadIdx.x;
    const int n0 = blockIdx.x * 16;

    for (int idx = tid; idx < 16 * FIN; idx += 128) {
        int e = idx / FIN, k = idx - e * FIN;
        s_in[idx] = nf[(n0 + e) * FIN + k];
    }
    __syncthreads();

    const int j = tid;
    float acc[16];
#pragma unroll
    for (int e = 0; e < 16; e++) acc[e] = 0.0f;
    for (int k = 0; k < FIN; k++) {
        float w = W1[k * DD + j];
#pragma unroll
        for (int e = 0; e < 16; e++) acc[e] = fmaf(s_in[e * FIN + k], w, acc[e]);
    }
    float bb1 = b1[j];
#pragma unroll
    for (int e = 0; e < 16; e++) s_hid[e * DD + j] = silu_f(acc[e] + bb1);
    __syncthreads();

    float acc2[16];
#pragma unroll
    for (int e = 0; e < 16; e++) acc2[e] = 0.0f;
    const float4* sh4 = (const float4*)s_hid;
    for (int k4 = 0; k4 < DD / 4; k4++) {
        const float* wp = &W2[(k4 * 4) * DD + j];
        float w0 = wp[0], w1 = wp[DD], w2 = wp[2 * DD], w3 = wp[3 * DD];
#pragma unroll
        for (int e = 0; e < 16; e++) {
            float4 a = sh4[e * (DD / 4) + k4];
            acc2[e] = fmaf(a.x, w0, acc2[e]);
            acc2[e] = fmaf(a.y, w1, acc2[e]);
            acc2[e] = fmaf(a.z, w2, acc2[e]);
            acc2[e] = fmaf(a.w, w3, acc2[e]);
        }
    }
    float bb2 = b2[j];
#pragma unroll
    for (int e = 0; e < 16; e++) h[(n0 + e) * DD + j] = acc2[e] + bb2;
}

// ---------------- fp16 A-fragment staging helper -----------------------------
__device__ __forceinline__ void stage_f4(unsigned int* sAu, int KC, int mt, int r,
                                         int k0, float4 v) {
    int kc = k0 >> 4;
    int c0 = k0 & 15;
    int t0 = ((r & 7) << 2) + ((c0 & 7) >> 1);
    int ii = (r >> 3) + ((c0 & 8) ? 2 : 0);
    unsigned int* base = sAu + ((mt * KC + kc) * 32) * 4 + ii;
    base[t0 * 4]       = packh2(v.x, v.y);
    base[(t0 + 1) * 4] = packh2(v.z, v.w);
}

// ---------------- fp16 tensor-core message MLP + v4-red scatter --------------
// CTA: 128 edges, 512 threads = 16 warps. Target 2 CTAs/SM (64 regs/thread).
// GEMM1: 1M x 16N warp grid, split into TWO M-passes (4 m-tiles each,
//        acc[4][2][4] = 32 regs) to fit the register budget.
// GEMM2: 2M x 8N.
__global__ void __launch_bounds__(512, 2) msg_mma_k(
    const int* __restrict__ EI, const float* __restrict__ pos,
    const float* __restrict__ h,
    const unsigned int* __restrict__ W1f, const float* __restrict__ b1,
    const unsigned int* __restrict__ W2f, const float* __restrict__ b2,
    float* __restrict__ agg)
{
    extern __shared__ __align__(16) unsigned int sAu[];   // 69632 B (KC1H layout)
    float* sAf = (float*)sAu;
    __shared__ float s_b1[HH];
    __shared__ float s_b2[DD];
    __shared__ int   s_dst[128];

    const int tid = threadIdx.x;
    const int e0 = blockIdx.x * 128;

    if (tid < HH) s_b1[tid] = b1[tid];
    if (tid < DD) s_b2[tid] = b2[tid];
    if (tid < 128) s_dst[tid] = EI[EE + e0 + tid];

    // ---- stage gathered edge features into fp16 A-fragment layout ----
    {
        const int e = tid >> 2;
        const int q = tid & 3;
        const int src = EI[e0 + e];
        const int dst = EI[EE + e0 + e];
        const float* hs = h + (size_t)src * DD;
        const float* hd = h + (size_t)dst * DD;
        const int r = e & 15, mt = e >> 4;
#pragma unroll
        for (int j = 0; j < 16; j++) {
            int k0 = j * 16 + q * 4;
            float4 v = (k0 < 128) ? *(const float4*)(hs + k0)
                                  : *(const float4*)(hd + (k0 - 128));
            stage_f4(sAu, KC1H, mt, r, k0, v);
        }
        // chunk kc=16: RBF features (4 values per staging thread)
        float dx = pos[dst * 3 + 0] - pos[src * 3 + 0];
        float dy = pos[dst * 3 + 1] - pos[src * 3 + 1];
        float dz = pos[dst * 3 + 2] - pos[src * 3 + 2];
        float dist = sqrtf(dx * dx + dy * dy + dz * dz + 1e-12f);
        float env = (dist < 10.0f)
                        ? 0.5f * (cosf(3.14159265358979323846f * dist * 0.1f) + 1.0f)
                        : 0.0f;
        const float inv2w2 = 1.0f / (2.0f * 0.625f * 0.625f);
        float rv[4];
#pragma unroll
        for (int kk = 0; kk < 4; kk++) {
            float c = (10.0f / 15.0f) * (float)(q * 4 + kk);
            float t = dist - c;
            rv[kk] = __expf(-t * t * inv2w2) * env;
        }
        stage_f4(sAu, KC1H, mt, r, 256 + q * 4,
                 make_float4(rv[0], rv[1], rv[2], rv[3]));
    }
    __syncthreads();

    const int wid = tid >> 5, lane = tid & 31;

    // ================= GEMM1: 1M x 16N, two M-passes of 4 m-tiles ===========
#pragma unroll 1
    for (int mp = 0; mp < 2; mp++) {
        float acc[4][2][4];
#pragma unroll
        for (int a = 0; a < 4; a++)
#pragma unroll
            for (int b = 0; b < 2; b++)
#pragma unroll
                for (int c = 0; c < 4; c++) acc[a][b][c] = 0.0f;
        {
            const uint4* ap = (const uint4*)sAu + (mp * 4) * KC1H * 32 + lane;
            const uint4* bp = (const uint4*)W1f + wid * 32 + lane;
#pragma unroll 1
            for (int kc = 0; kc < KC1H; kc++) {
                uint4 b = bp[kc * 512];
#pragma unroll
                for (int mi = 0; mi < 4; mi++) {
                    uint4 a = ap[(mi * KC1H + kc) * 32];
                    mma16(acc[mi][0], a, b.x, b.y);
                    mma16(acc[mi][1], a, b.z, b.w);
                }
            }
        }
        __syncthreads();   // all pass-mp MMAs done before overwriting A1 region

        // epilogue: bias + silu -> A2 fp16 fragment layout (KC2H), m-tiles mp*4..mp*4+3
#pragma unroll
        for (int mi = 0; mi < 4; mi++)
#pragma unroll
            for (int nf = 0; nf < 2; nf++) {
                int mg = mp * 4 + mi;
                int m_lo = (lane >> 2);
                int n = wid * 16 + nf * 8 + ((lane & 3) << 1);
                float y00 = silu_f(acc[mi][nf][0] + s_b1[n]);
                float y01 = silu_f(acc[mi][nf][1] + s_b1[n + 1]);
                float y10 = silu_f(acc[mi][nf][2] + s_b1[n]);
                float y11 = silu_f(acc[mi][nf][3] + s_b1[n + 1]);
                int kc2 = n >> 4, c2 = n & 15;
                int t2 = ((m_lo & 7) << 2) + ((c2 & 7) >> 1);
                int ib = (c2 & 8) ? 2 : 0;
                unsigned int* base = sAu + ((mg * KC2H + kc2) * 32 + t2) * 4 + ib;
                base[0] = packh2(y00, y01);
                base[1] = packh2(y10, y11);
            }
    }
    __syncthreads();

    // ================= GEMM2: 2M x 8N ======================================
    const int wm = wid >> 3, wn = wid & 7;
    float acc2[4][2][4];
#pragma unroll
    for (int a = 0; a < 4; a++)
#pragma unroll
        for (int b = 0; b < 2; b++)
#pragma unroll
            for (int c = 0; c < 4; c++) acc2[a][b][c] = 0.0f;
    {
        const uint4* ap0 = (const uint4*)sAu + (wm * 4 + 0) * KC2H * 32 + lane;
        const uint4* ap1 = (const uint4*)sAu + (wm * 4 + 1) * KC2H * 32 + lane;
        const uint4* ap2 = (const uint4*)sAu + (wm * 4 + 2) * KC2H * 32 + lane;
        const uint4* ap3 = (const uint4*)sAu + (wm * 4 + 3) * KC2H * 32 + lane;
        const uint4* bp = (const uint4*)W2f + wn * 32 + lane;
#pragma unroll 2
        for (int kc = 0; kc < KC2H; kc++) {
            uint4 b = bp[kc * 256];
            uint4 a0 = ap0[kc * 32], a1 = ap1[kc * 32];
            uint4 a2 = ap2[kc * 32], a3 = ap3[kc * 32];
            mma16(acc2[0][0], a0, b.x, b.y);  mma16(acc2[0][1], a0, b.z, b.w);
            mma16(acc2[1][0], a1, b.x, b.y);  mma16(acc2[1][1], a1, b.z, b.w);
            mma16(acc2[2][0], a2, b.x, b.y);  mma16(acc2[2][1], a2, b.z, b.w);
            mma16(acc2[3][0], a3, b.x, b.y);  mma16(acc2[3][1], a3, b.z, b.w);
        }
    }
    __syncthreads();   // region reused as fp32 D2 staging [128][132]

    // ---- epilogue2: stage D2+bias, then red.v4 scatter ----
#pragma unroll
    for (int mi = 0; mi < 4; mi++)
#pragma unroll
        for (int nf = 0; nf < 2; nf++)
#pragma unroll
            for (int j = 0; j < 4; j++) {
                int m = wm * 64 + mi * 16 + (lane >> 2) + ((j >> 1) << 3);
                int n = wn * 16 + nf * 8 + ((lane & 3) << 1) + (j & 1);
                sAf[m * 132 + n] = acc2[mi][nf][j] + s_b2[n];
            }
    __syncthreads();
    {
        const int cc = tid & 31;
        const int r0 = tid >> 5;
#pragma unroll
        for (int it = 0; it < 8; it++) {
            int r = r0 + it * 16;
            float4 v = *(const float4*)(sAf + r * 132 + cc * 4);
            red4(agg + (size_t)s_dst[r] * DD + cc * 4, v);
        }
    }
}

// ---------------- fp16 tensor-core update MLP (residual) ---------------------
// CTA: 128 nodes, 512 threads. GEMM1: 1M x 16N; GEMM2: 2M x 8N.
__global__ void __launch_bounds__(512, 1) upd_mma_k(
    float* __restrict__ h, const float* __restrict__ agg,
    const unsigned int* __restrict__ W1f, const float* __restrict__ b1,
    const unsigned int* __restrict__ W2f, const float* __restrict__ b2)
{
    extern __shared__ __align__(16) unsigned int sAu[];   // 69632 B
    float* sAf = (float*)sAu;
    __shared__ float s_b1[HH];
    __shared__ float s_b2[DD];

    const int tid = threadIdx.x;
    const int n0 = blockIdx.x * 128;

    if (tid < HH) s_b1[tid] = b1[tid];
    if (tid < DD) s_b2[tid] = b2[tid];

    {
        const int e = tid >> 2, q = tid & 3;
        const float* hs = h + (size_t)(n0 + e) * DD;
        const float* ag = agg + (size_t)(n0 + e) * DD;
        const int r = e & 15, mt = e >> 4;
#pragma unroll
        for (int j = 0; j < 16; j++) {
            int k0 = j * 16 + q * 4;
            float4 v = (k0 < 128) ? *(const float4*)(hs + k0)
                                  : *(const float4*)(ag + (k0 - 128));
            stage_f4(sAu, 16, mt, r, k0, v);
        }
    }
    __syncthreads();

    const int wid = tid >> 5, lane = tid & 31;

    // GEMM1: 1M x 16N
    float acc[8][2][4];
#pragma unroll
    for (int a = 0; a < 8; a++)
#pragma unroll
        for (int b = 0; b < 2; b++)
#pragma unroll
            for (int c = 0; c < 4; c++) acc[a][b][c] = 0.0f;
    {
        const uint4* ap = (const uint4*)sAu + lane;
        const uint4* bp = (const uint4*)W1f + wid * 32 + lane;
#pragma unroll 1
        for (int kc = 0; kc < 16; kc++) {
            uint4 b = bp[kc * 512];
#pragma unroll
            for (int mi = 0; mi < 8; mi++) {
                uint4 a = ap[(mi * 16 + kc) * 32];
                mma16(acc[mi][0], a, b.x, b.y);
                mma16(acc[mi][1], a, b.z, b.w);
            }
        }
    }
    __syncthreads();

#pragma unroll
    for (int mi = 0; mi < 8; mi++)
#pragma unroll
        for (int nf = 0; nf < 2; nf++) {
            int m_lo = mi * 16 + (lane >> 2);
            int n = wid * 16 + nf * 8 + ((lane & 3) << 1);
            float y00 = silu_f(acc[mi][nf][0] + s_b1[n]);
            float y01 = silu_f(acc[mi][nf][1] + s_b1[n + 1]);
            float y10 = silu_f(acc[mi][nf][2] + s_b1[n]);
            float y11 = silu_f(acc[mi][nf][3] + s_b1[n + 1]);
            int kc2 = n >> 4, c2 = n & 15;
            int t2 = ((m_lo & 7) << 2) + ((c2 & 7) >> 1);
            int ib = (c2 & 8) ? 2 : 0;
            unsigned int* base = sAu + ((mi * 16 + kc2) * 32 + t2) * 4 + ib;
            base[0] = packh2(y00, y01);
            base[1] = packh2(y10, y11);
        }
    __syncthreads();

    // GEMM2: 2M x 8N
    const int wm = wid >> 3, wn = wid & 7;
    float acc2[4][2][4];
#pragma unroll
    for (int a = 0; a < 4; a++)
#pragma unroll
        for (int b = 0; b < 2; b++)
#pragma unroll
            for (int c = 0; c < 4; c++) acc2[a][b][c] = 0.0f;
    {
        const uint4* ap0 = (const uint4*)sAu + (wm * 4 + 0) * 16 * 32 + lane;
        const uint4* ap1 = (const uint4*)sAu + (wm * 4 + 1) * 16 * 32 + lane;
        const uint4* ap2 = (const uint4*)sAu + (wm * 4 + 2) * 16 * 32 + lane;
        const uint4* ap3 = (const uint4*)sAu + (wm * 4 + 3) * 16 * 32 + lane;
        const uint4* bp = (const uint4*)W2f + wn * 32 + lane;
#pragma unroll 2
        for (int kc = 0; kc < 16; kc++) {
            uint4 b = bp[kc * 256];
            uint4 a0 = ap0[kc * 32], a1 = ap1[kc * 32];
            uint4 a2 = ap2[kc * 32], a3 = ap3[kc * 32];
            mma16(acc2[0][0], a0, b.x, b.y);  mma16(acc2[0][1], a0, b.z, b.w);
            mma16(acc2[1][0], a1, b.x, b.y);  mma16(acc2[1][1], a1, b.z, b.w);
            mma16(acc2[2][0], a2, b.x, b.y);  mma16(acc2[2][1], a2, b.z, b.w);
            mma16(acc2[3][0], a3, b.x, b.y);  mma16(acc2[3][1], a3, b.z, b.w);
        }
    }
    __syncthreads();

#pragma unroll
    for (int mi = 0; mi < 4; mi++)
#pragma unroll
        for (int nf = 0; nf < 2; nf++)
#pragma unroll
            for (int j = 0; j < 4; j++) {
                int m = wm * 64 + mi * 16 + (lane >> 2) + ((j >> 1) << 3);
                int n = wn * 16 + nf * 8 + ((lane & 3) << 1) + (j & 1);
                sAf[m * 132 + n] = acc2[mi][nf][j] + s_b2[n];
            }
    __syncthreads();
    {
        const int cc = tid & 31;
        const int r0 = tid >> 5;
#pragma unroll
        for (int it = 0; it < 8; it++) {
            int r = r0 + it * 16;
            float4 v = *(const float4*)(sAf + r * 132 + cc * 4);
            float* hp = h + (size_t)(n0 + r) * DD + cc * 4;
            float4 o = *(float4*)hp;
            o.x += v.x; o.y += v.y; o.z += v.z; o.w += v.w;
            *(float4*)hp = o;
        }
    }
}

// ---------------- per-graph counts ------------------------------------------
__global__ void cnt_k(const int* __restrict__ batch, float* __restrict__ cnt)
{
    int n = blockIdx.x * blockDim.x + threadIdx.x;
    if (n < NN) atomicAdd(&cnt[batch[n]], 1.0f);
}

// ---------------- per-graph feature sums ------------------------------------
__global__ void __launch_bounds__(128) gsum_k(
    const float* __restrict__ h, const int* __restrict__ batch,
    float* __restrict__ gsum)
{
    const int j = threadIdx.x;
    const int n0 = blockIdx.x * 32;
    int curb = batch[n0];
    float acc = 0.0f;
    for (int i = 0; i < 32; i++) {
        int n = n0 + i;
        int b = batch[n];
        if (b != curb) {
            atomicAdd(&gsum[curb * DD + j], acc);
            acc = 0.0f;
            curb = b;
        }
        acc += h[n * DD + j];
    }
    atomicAdd(&gsum[curb * DD + j], acc);
}

// ---------------- readout MLP (single block) --------------------------------
__global__ void __launch_bounds__(256) final_k(
    const float* __restrict__ gsum, const float* __restrict__ cnt,
    const float* __restrict__ W1, const float* __restrict__ b1,
    const float* __restrict__ W2, const float* __restrict__ b2,
    float* __restrict__ out)
{
    __shared__ float sg[BB * DD];
    __shared__ float sh[BB * HH];
    const int tid = threadIdx.x;

    for (int idx = tid; idx < BB * DD; idx += 256) {
        int b = idx >> 7;
        sg[idx] = gsum[idx] / fmaxf(cnt[b], 1.0f);
    }
    __syncthreads();

    {
        const int j = tid;
        float acc[BB];
#pragma unroll
        for (int b = 0; b < BB; b++) acc[b] = 0.0f;
        for (int k = 0; k < DD; k++) {
            float w = W1[k * HH + j];
#pragma unroll
            for (int b = 0; b < BB; b++) acc[b] = fmaf(sg[b * DD + k], w, acc[b]);
        }
        float bb = b1[j];
#pragma unroll
        for (int b = 0; b < BB; b++) sh[b * HH + j] = silu_f(acc[b] + bb);
    }
    __syncthreads();

    if (tid < OUTD) {
        const int j = tid;
        float acc[BB];
#pragma unroll
        for (int b = 0; b < BB; b++) acc[b] = 0.0f;
        for (int k = 0; k < HH; k++) {
            float w = W2[k * OUTD + j];
#pragma unroll
            for (int b = 0; b < BB; b++) acc[b] = fmaf(sh[b * HH + k], w, acc[b]);
        }
        float bb = b2[j];
#pragma unroll
        for (int b = 0; b < BB; b++) out[b * OUTD + j] = acc[b] + bb;
    }
}

// ---------------- launch -----------------------------------------------------
#define SMEM_MSG (8 * KC1H * 32 * 4 * 4)   // 69632 bytes
#define SMEM_UPD 69632

extern "C" void kernel_launch(void* const* d_in, const int* in_sizes, int n_in,
                              void* d_out, int out_size)
{
    const float* pos    = (const float*)d_in[0];
    const float* nf     = (const float*)d_in[1];
    const int*   EI     = (const int*)d_in[2];
    const int*   batch  = (const int*)d_in[3];
    const float* emb_W1 = (const float*)d_in[4];
    const float* emb_b1 = (const float*)d_in[5];
    const float* emb_W2 = (const float*)d_in[6];
    const float* emb_b2 = (const float*)d_in[7];
    const float* msg_W1 = (const float*)d_in[8];
    const float* msg_b1 = (const float*)d_in[9];
    const float* msg_W2 = (const float*)d_in[10];
    const float* msg_b2 = (const float*)d_in[11];
    const float* upd_W1 = (const float*)d_in[12];
    const float* upd_b1 = (const float*)d_in[13];
    const float* upd_W2 = (const float*)d_in[14];
    const float* upd_b2 = (const float*)d_in[15];
    const float* r_W1   = (const float*)d_in[16];
    const float* r_b1   = (const float*)d_in[17];
    const float* r_W2   = (const float*)d_in[18];
    const float* r_b2   = (const float*)d_in[19];
    float* out = (float*)d_out;

    void *p_h, *p_agg, *p_gsum, *p_gcnt, *p_w1f, *p_w2f, *p_wu1f, *p_wu2f;
    cudaGetSymbolAddress(&p_h, g_h);
    cudaGetSymbolAddress(&p_agg, g_agg);
    cudaGetSymbolAddress(&p_gsum, g_gsum);
    cudaGetSymbolAddress(&p_gcnt, g_gcnt);
    cudaGetSymbolAddress(&p_w1f, g_W1f);
    cudaGetSymbolAddress(&p_w2f, g_W2f);
    cudaGetSymbolAddress(&p_wu1f, g_WU1f);
    cudaGetSymbolAddress(&p_wu2f, g_WU2f);
    float* h    = (float*)p_h;
    float* agg  = (float*)p_agg;
    float* gsum = (float*)p_gsum;
    float* gcnt = (float*)p_gcnt;
    unsigned int* W1f  = (unsigned int*)p_w1f;
    unsigned int* W2f  = (unsigned int*)p_w2f;
    unsigned int* WU1f = (unsigned int*)p_wu1f;
    unsigned int* WU2f = (unsigned int*)p_wu2f;

    cudaFuncSetAttribute(msg_mma_k, cudaFuncAttributeMaxDynamicSharedMemorySize, SMEM_MSG);
    cudaFuncSetAttribute(upd_mma_k, cudaFuncAttributeMaxDynamicSharedMemorySize, SMEM_UPD);

    prep1_k<<<(NL * KC1H * 16 * 32 * 4 + 255) / 256, 256>>>(msg_W1, W1f);
    prep2_k<<<(NL * KC2H * 8 * 32 * 4 + 255) / 256, 256>>>(msg_W2, W2f);
    prepU1_k<<<(NL * 16 * 16 * 32 * 4 + 255) / 256, 256>>>(upd_W1, WU1f);
    prepU2_k<<<(NL * 16 * 8 * 32 * 4 + 255) / 256, 256>>>(upd_W2, WU2f);
    embed_k<<<NN / 16, 128>>>(nf, emb_W1, emb_b1, emb_W2, emb_b2, h);

    for (int l = 0; l < NL; l++) {
        cudaMemsetAsync(agg, 0, (size_t)NN * DD * sizeof(float), 0);
        msg_mma_k<<<EE / 128, 512, SMEM_MSG>>>(
            EI, pos, h,
            W1f + (size_t)l * KC1H * 16 * 32 * 4,
            msg_b1 + (size_t)l * HH,
            W2f + (size_t)l * KC2H * 8 * 32 * 4,
            msg_b2 + (size_t)l * DD,
            agg);
        upd_mma_k<<<NN / 128, 512, SMEM_UPD>>>(
            h, agg,
            WU1f + (size_t)l * 16 * 16 * 32 * 4,
            upd_b1 + (size_t)l * HH,
            WU2f + (size_t)l * 16 * 8 * 32 * 4,
            upd_b2 + (size_t)l * DD);
    }

    cudaMemsetAsync(gsum, 0, (size_t)BB * DD * sizeof(float), 0);
    cudaMemsetAsync(gcnt, 0, (size_t)BB * sizeof(float), 0);
    cnt_k<<<NN / 256, 256>>>(batch, gcnt);
    gsum_k<<<NN / 32, 128>>>(h, batch, gsum);
    final_k<<<1, 256>>>(gsum, gcnt, r_W1, r_b1, r_W2, r_b2, out);
}